// round 2
// baseline (speedup 1.0000x reference)
#include <cuda_runtime.h>

// Problem constants
#define B4   4      // 2*BS concatenated batch
#define Dd   256    // feature dim
#define D2   512
#define NN   1024   // keypoints
#define Hh   4
#define HD   64
#define LL   6

// Scratch (device globals; no allocation allowed)
__device__ float g_Q[B4 * Dd * NN];
__device__ float g_K[B4 * Dd * NN];
__device__ float g_V[B4 * Dd * NN];
__device__ float g_S[16 * NN * NN];      // [b*h][n][m]  64 MB
__device__ float g_Xatt[B4 * Dd * NN];
__device__ float g_Msg[B4 * Dd * NN];
__device__ float g_Y1[B4 * D2 * NN];
__device__ float g_scale[D2];
__device__ float g_shift[D2];

// ---------------------------------------------------------------------------
// Generic conv1x1 GEMM: Out[b][o][n] = sum_i W[o][i] * X[b^xorMask][i][n] + bias[o]
// If X2 != nullptr: channels [0,256) read from X (batch stride 256*NN),
// channels [256,I) from X2 (concat along channel dim), xorMask ignored.
// addOut: Out += result (residual add).
// Block: 16x16 threads, 64x64 output tile, 4x4 per thread, K-tile 16.
// ---------------------------------------------------------------------------
__global__ __launch_bounds__(256) void conv_gemm(
    const float* __restrict__ W, const float* __restrict__ bias,
    const float* __restrict__ X, const float* __restrict__ X2,
    int I, int xorMask, float* __restrict__ Out, int O, int addOut)
{
    int b    = blockIdx.z;
    int row0 = blockIdx.y * 64;
    int col0 = blockIdx.x * 64;
    int tx = threadIdx.x, ty = threadIdx.y;
    int t  = ty * 16 + tx;

    __shared__ float Ws[64][17];   // [row][k]
    __shared__ float Xs[16][64];   // [k][col]

    const float* XbA;
    const float* XbB = nullptr;
    if (X2) {
        XbA = X  + (size_t)b * 256 * NN;
        XbB = X2 + (size_t)b * 256 * NN;
    } else {
        XbA = X + (size_t)(b ^ xorMask) * (size_t)I * NN;
    }

    float acc[4][4] = {};

    for (int k0 = 0; k0 < I; k0 += 16) {
        #pragma unroll
        for (int u = 0; u < 4; u++) {
            int idx = t + 256 * u;
            int r = idx >> 4, k = idx & 15;
            Ws[r][k] = W[(size_t)(row0 + r) * I + k0 + k];
        }
        #pragma unroll
        for (int u = 0; u < 4; u++) {
            int idx = t + 256 * u;
            int k = idx >> 6, c = idx & 63;
            int ch = k0 + k;
            const float* src = XbA;
            int chl = ch;
            if (XbB && ch >= 256) { src = XbB; chl = ch - 256; }
            Xs[k][c] = src[(size_t)chl * NN + col0 + c];
        }
        __syncthreads();

        #pragma unroll
        for (int k = 0; k < 16; k++) {
            float a0 = Ws[ty * 4 + 0][k];
            float a1 = Ws[ty * 4 + 1][k];
            float a2 = Ws[ty * 4 + 2][k];
            float a3 = Ws[ty * 4 + 3][k];
            float4 bv = *(const float4*)&Xs[k][tx * 4];
            acc[0][0] += a0 * bv.x; acc[0][1] += a0 * bv.y; acc[0][2] += a0 * bv.z; acc[0][3] += a0 * bv.w;
            acc[1][0] += a1 * bv.x; acc[1][1] += a1 * bv.y; acc[1][2] += a1 * bv.z; acc[1][3] += a1 * bv.w;
            acc[2][0] += a2 * bv.x; acc[2][1] += a2 * bv.y; acc[2][2] += a2 * bv.z; acc[2][3] += a2 * bv.w;
            acc[3][0] += a3 * bv.x; acc[3][1] += a3 * bv.y; acc[3][2] += a3 * bv.z; acc[3][3] += a3 * bv.w;
        }
        __syncthreads();
    }

    float* Ob = Out + (size_t)b * O * NN;
    #pragma unroll
    for (int i = 0; i < 4; i++) {
        int row = row0 + ty * 4 + i;
        float bb = bias[row];
        #pragma unroll
        for (int j = 0; j < 4; j++) {
            int col = col0 + tx * 4 + j;
            float v = acc[i][j] + bb;
            if (addOut) Ob[(size_t)row * NN + col] += v;
            else        Ob[(size_t)row * NN + col] = v;
        }
    }
}

// ---------------------------------------------------------------------------
// Attention scores: S[bh][n][m] = (1/8) * sum_d Q[b][(d*4+h)][n] * K[b][(d*4+h)][m]
// ---------------------------------------------------------------------------
__global__ __launch_bounds__(256) void scores_kernel(
    const float* __restrict__ Q, const float* __restrict__ Kx, float* __restrict__ S)
{
    int bh = blockIdx.z; int b = bh >> 2, h = bh & 3;
    int n0 = blockIdx.y * 64, m0 = blockIdx.x * 64;
    int tx = threadIdx.x, ty = threadIdx.y;
    int t  = ty * 16 + tx;

    const float* Qb = Q  + (size_t)b * Dd * NN;
    const float* Kb = Kx + (size_t)b * Dd * NN;

    __shared__ float Qs[16][64];
    __shared__ float Ks[16][64];

    float acc[4][4] = {};

    for (int k0 = 0; k0 < HD; k0 += 16) {
        #pragma unroll
        for (int u = 0; u < 4; u++) {
            int idx = t + 256 * u;
            int k = idx >> 6, c = idx & 63;
            int ch = (k0 + k) * 4 + h;
            Qs[k][c] = Qb[(size_t)ch * NN + n0 + c];
            Ks[k][c] = Kb[(size_t)ch * NN + m0 + c];
        }
        __syncthreads();
        #pragma unroll
        for (int k = 0; k < 16; k++) {
            float4 av = *(const float4*)&Qs[k][ty * 4];
            float4 bv = *(const float4*)&Ks[k][tx * 4];
            acc[0][0] += av.x * bv.x; acc[0][1] += av.x * bv.y; acc[0][2] += av.x * bv.z; acc[0][3] += av.x * bv.w;
            acc[1][0] += av.y * bv.x; acc[1][1] += av.y * bv.y; acc[1][2] += av.y * bv.z; acc[1][3] += av.y * bv.w;
            acc[2][0] += av.z * bv.x; acc[2][1] += av.z * bv.y; acc[2][2] += av.z * bv.z; acc[2][3] += av.z * bv.w;
            acc[3][0] += av.w * bv.x; acc[3][1] += av.w * bv.y; acc[3][2] += av.w * bv.z; acc[3][3] += av.w * bv.w;
        }
        __syncthreads();
    }

    float* Sp = S + (size_t)bh * NN * NN;
    #pragma unroll
    for (int i = 0; i < 4; i++)
        #pragma unroll
        for (int j = 0; j < 4; j++)
            Sp[(size_t)(n0 + ty * 4 + i) * NN + m0 + tx * 4 + j] = acc[i][j] * 0.125f;
}

// ---------------------------------------------------------------------------
// Fused multiplicative-mask + softmax over last dim (1024). One block per row.
// ---------------------------------------------------------------------------
__global__ __launch_bounds__(256) void softmax_kernel(
    float* __restrict__ S, const float* __restrict__ M0, const float* __restrict__ M1)
{
    int r  = blockIdx.x;           // bh*1024 + n
    int n  = r & 1023;
    int bh = r >> 10;
    int b  = bh >> 2;
    float* Sp = S + (size_t)r * NN;
    const float* Mp = (b < 2 ? M0 + (size_t)b * NN * NN
                             : M1 + (size_t)(b - 2) * NN * NN) + (size_t)n * NN;

    int t = threadIdx.x;
    float v[4];
    float mx = -1e30f;
    #pragma unroll
    for (int j = 0; j < 4; j++) {
        int m = t + j * 256;
        v[j] = Sp[m] * Mp[m];
        mx = fmaxf(mx, v[j]);
    }
    __shared__ float red[256];
    red[t] = mx; __syncthreads();
    #pragma unroll
    for (int s = 128; s > 0; s >>= 1) {
        if (t < s) red[t] = fmaxf(red[t], red[t + s]);
        __syncthreads();
    }
    mx = red[0];
    __syncthreads();

    float sum = 0.f;
    #pragma unroll
    for (int j = 0; j < 4; j++) { v[j] = __expf(v[j] - mx); sum += v[j]; }
    red[t] = sum; __syncthreads();
    #pragma unroll
    for (int s = 128; s > 0; s >>= 1) {
        if (t < s) red[t] += red[t + s];
        __syncthreads();
    }
    float inv = 1.0f / red[0];
    #pragma unroll
    for (int j = 0; j < 4; j++) Sp[t + j * 256] = v[j] * inv;
}

// ---------------------------------------------------------------------------
// AV: Xatt[b][(d*4+h)][n] = sum_m P[bh][n][m] * V[b][(d*4+h)][m]
// One block: full d-range (64) x 64 n-cols; K loop over m (1024).
// ---------------------------------------------------------------------------
__global__ __launch_bounds__(256) void av_kernel(
    const float* __restrict__ P, const float* __restrict__ V, float* __restrict__ Xatt)
{
    int bh = blockIdx.y; int b = bh >> 2, h = bh & 3;
    int n0 = blockIdx.x * 64;
    int tx = threadIdx.x, ty = threadIdx.y;
    int t  = ty * 16 + tx;

    const float* Pb = P + (size_t)bh * NN * NN;
    const float* Vb = V + (size_t)b * Dd * NN;

    __shared__ float Vs[64][17];   // [d][k]
    __shared__ float Ps[64][17];   // [n][k]

    float acc[4][4] = {};

    for (int m0 = 0; m0 < NN; m0 += 16) {
        #pragma unroll
        for (int u = 0; u < 4; u++) {
            int idx = t + 256 * u;
            int rr = idx >> 4, k = idx & 15;
            Vs[rr][k] = Vb[(size_t)(rr * 4 + h) * NN + m0 + k];
            Ps[rr][k] = Pb[(size_t)(n0 + rr) * NN + m0 + k];
        }
        __syncthreads();
        #pragma unroll
        for (int k = 0; k < 16; k++) {
            float a0 = Vs[ty * 4 + 0][k];
            float a1 = Vs[ty * 4 + 1][k];
            float a2 = Vs[ty * 4 + 2][k];
            float a3 = Vs[ty * 4 + 3][k];
            float b0 = Ps[tx * 4 + 0][k];
            float b1 = Ps[tx * 4 + 1][k];
            float b2 = Ps[tx * 4 + 2][k];
            float b3 = Ps[tx * 4 + 3][k];
            acc[0][0] += a0 * b0; acc[0][1] += a0 * b1; acc[0][2] += a0 * b2; acc[0][3] += a0 * b3;
            acc[1][0] += a1 * b0; acc[1][1] += a1 * b1; acc[1][2] += a1 * b2; acc[1][3] += a1 * b3;
            acc[2][0] += a2 * b0; acc[2][1] += a2 * b1; acc[2][2] += a2 * b2; acc[2][3] += a2 * b3;
            acc[3][0] += a3 * b0; acc[3][1] += a3 * b1; acc[3][2] += a3 * b2; acc[3][3] += a3 * b3;
        }
        __syncthreads();
    }

    float* Xb = Xatt + (size_t)b * Dd * NN;
    #pragma unroll
    for (int i = 0; i < 4; i++) {
        int ch = (ty * 4 + i) * 4 + h;
        #pragma unroll
        for (int j = 0; j < 4; j++)
            Xb[(size_t)ch * NN + n0 + tx * 4 + j] = acc[i][j];
    }
}

// ---------------------------------------------------------------------------
// BatchNorm1d (training mode): stats over (B=4, N=1024) per channel.
// ---------------------------------------------------------------------------
__global__ __launch_bounds__(256) void bn_stats(
    const float* __restrict__ Y, const float* __restrict__ g, const float* __restrict__ beta)
{
    int c = blockIdx.x;
    int t = threadIdx.x;
    float s = 0.f, sq = 0.f;
    for (int b = 0; b < 4; b++) {
        const float* Yp = Y + (size_t)b * D2 * NN + (size_t)c * NN;
        for (int n = t; n < NN; n += 256) {
            float v = Yp[n];
            s += v; sq += v * v;
        }
    }
    __shared__ float rs[256], rq[256];
    rs[t] = s; rq[t] = sq; __syncthreads();
    #pragma unroll
    for (int st = 128; st > 0; st >>= 1) {
        if (t < st) { rs[t] += rs[t + st]; rq[t] += rq[t + st]; }
        __syncthreads();
    }
    if (t == 0) {
        float mean = rs[0] * (1.0f / 4096.0f);
        float var  = rq[0] * (1.0f / 4096.0f) - mean * mean;
        float rstd = rsqrtf(var + 1e-5f);
        float sc = g[c] * rstd;
        g_scale[c] = sc;
        g_shift[c] = beta[c] - mean * sc;
    }
}

__global__ __launch_bounds__(256) void bn_relu(float* __restrict__ Y)
{
    int i = blockIdx.x * 256 + threadIdx.x;   // 4*512*1024 total
    int c = (i >> 10) & 511;
    float v = Y[i] * g_scale[c] + g_shift[c];
    Y[i] = v > 0.f ? v : 0.f;
}

// ---------------------------------------------------------------------------
extern "C" void kernel_launch(void* const* d_in, const int* in_sizes, int n_in,
                              void* d_out, int out_size)
{
    const float* desc0 = (const float*)d_in[0];
    const float* desc1 = (const float*)d_in[1];
    const float* M0    = (const float*)d_in[2];
    const float* M1    = (const float*)d_in[3];
    const float* Wq = (const float*)d_in[4];
    const float* bq = (const float*)d_in[5];
    const float* Wk = (const float*)d_in[6];
    const float* bk = (const float*)d_in[7];
    const float* Wv = (const float*)d_in[8];
    const float* bv = (const float*)d_in[9];
    const float* Wm = (const float*)d_in[10];
    const float* bm = (const float*)d_in[11];
    const float* W1 = (const float*)d_in[12];
    const float* b1 = (const float*)d_in[13];
    const float* g1 = (const float*)d_in[14];
    const float* be1 = (const float*)d_in[15];
    const float* W2 = (const float*)d_in[16];
    const float* b2 = (const float*)d_in[17];

    float* Dsc = (float*)d_out;   // [4, 256, 1024] — doubles as the output

    float *Q, *K, *V, *S, *Xatt, *Msg, *Y1;
    cudaGetSymbolAddress((void**)&Q,    g_Q);
    cudaGetSymbolAddress((void**)&K,    g_K);
    cudaGetSymbolAddress((void**)&V,    g_V);
    cudaGetSymbolAddress((void**)&S,    g_S);
    cudaGetSymbolAddress((void**)&Xatt, g_Xatt);
    cudaGetSymbolAddress((void**)&Msg,  g_Msg);
    cudaGetSymbolAddress((void**)&Y1,   g_Y1);

    size_t descBytes = (size_t)2 * Dd * NN * sizeof(float);
    cudaMemcpyAsync(Dsc,               desc0, descBytes, cudaMemcpyDeviceToDevice, 0);
    cudaMemcpyAsync(Dsc + 2 * Dd * NN, desc1, descBytes, cudaMemcpyDeviceToDevice, 0);

    dim3 blk(16, 16);
    static const int crossFlag[LL] = {0, 1, 0, 1, 0, 1};

    for (int i = 0; i < LL; i++) {
        int xm = crossFlag[i] ? 2 : 0;
        const float* Wqi = Wq + (size_t)i * Dd * Dd;
        const float* bqi = bq + (size_t)i * Dd;
        const float* Wki = Wk + (size_t)i * Dd * Dd;
        const float* bki = bk + (size_t)i * Dd;
        const float* Wvi = Wv + (size_t)i * Dd * Dd;
        const float* bvi = bv + (size_t)i * Dd;
        const float* Wmi = Wm + (size_t)i * Dd * Dd;
        const float* bmi = bm + (size_t)i * Dd;
        const float* W1i = W1 + (size_t)i * D2 * D2;
        const float* b1i = b1 + (size_t)i * D2;
        const float* g1i = g1 + (size_t)i * D2;
        const float* be1i = be1 + (size_t)i * D2;
        const float* W2i = W2 + (size_t)i * Dd * D2;
        const float* b2i = b2 + (size_t)i * Dd;

        // Q from x, K/V from src (= x for self, swapped halves for cross)
        conv_gemm<<<dim3(16, 4, 4), blk>>>(Wqi, bqi, Dsc, nullptr, Dd, 0,  Q, Dd, 0);
        conv_gemm<<<dim3(16, 4, 4), blk>>>(Wki, bki, Dsc, nullptr, Dd, xm, K, Dd, 0);
        conv_gemm<<<dim3(16, 4, 4), blk>>>(Wvi, bvi, Dsc, nullptr, Dd, xm, V, Dd, 0);

        scores_kernel<<<dim3(16, 16, 16), blk>>>(Q, K, S);
        softmax_kernel<<<16 * NN, 256>>>(S, M0, M1);
        av_kernel<<<dim3(16, 16), blk>>>(S, V, Xatt);

        // merge conv
        conv_gemm<<<dim3(16, 4, 4), blk>>>(Wmi, bmi, Xatt, nullptr, Dd, 0, Msg, Dd, 0);

        // MLP: conv1 (concat [x; msg] along channels), BN+relu, conv2 (+residual)
        conv_gemm<<<dim3(16, 8, 4), blk>>>(W1i, b1i, Dsc, Msg, D2, 0, Y1, D2, 0);
        bn_stats<<<D2, 256>>>(Y1, g1i, be1i);
        bn_relu<<<(B4 * D2 * NN) / 256, 256>>>(Y1);
        conv_gemm<<<dim3(16, 4, 4), blk>>>(W2i, b2i, Y1, nullptr, D2, 0, Dsc, Dd, 1);
    }
}

// round 3
// speedup vs baseline: 1.3845x; 1.3845x over previous
#include <cuda_runtime.h>

#define B4   4      // 2*BS concatenated batch
#define Dd   256    // feature dim
#define D2   512
#define NN   1024   // keypoints
#define HD   64
#define LL   6

// Scratch (device globals; no allocation allowed)
__device__ float g_Q[B4 * Dd * NN];
__device__ float g_K[B4 * Dd * NN];
__device__ float g_V[B4 * Dd * NN];
__device__ float g_Xatt[B4 * Dd * NN];
__device__ float g_Msg[B4 * Dd * NN];
__device__ float g_Y1[B4 * D2 * NN];
__device__ float g_scale[D2];
__device__ float g_shift[D2];

// ---------------------------------------------------------------------------
// conv1x1 GEMM: Out[b][o][n] = sum_i W[o][i] * X[b^xorMask][i][n] + bias[o]
// X2 != nullptr: channels [0,256) from X, [256,I) from X2 (channel concat).
// Tile: 64 (o) x 128 (n), 256 threads, 4x8 per thread, K-tile 16.
// Per-thread cols are {tx*4..+3} and {64+tx*4..+3} so all LDS are
// conflict-free float4.
// ---------------------------------------------------------------------------
__global__ __launch_bounds__(256) void conv_gemm(
    const float* __restrict__ W, const float* __restrict__ bias,
    const float* __restrict__ X, const float* __restrict__ X2,
    int I, int xorMask, float* __restrict__ Out, int addOut)
{
    __shared__ float As[16][68];    // [k][row], pad 68 keeps float4 alignment
    __shared__ float Xs[16][128];   // [k][col]

    int b    = blockIdx.z;
    int row0 = blockIdx.y * 64;
    int col0 = blockIdx.x * 128;
    int t  = threadIdx.x;
    int tx = t & 15, ty = t >> 4;

    const float* XA;
    const float* XB = nullptr;
    if (X2) {
        XA = X  + (size_t)b * Dd * NN;
        XB = X2 + (size_t)b * Dd * NN;
    } else {
        XA = X + (size_t)(b ^ xorMask) * (size_t)I * NN;
    }

    float acc[4][8] = {};

    int lr = t >> 2, lk = (t & 3) * 4;   // W-tile load mapping
    int xk = t >> 4, xc = (t & 15) * 8;  // X-tile load mapping

    for (int k0 = 0; k0 < I; k0 += 16) {
        // W tile (transpose to [k][row])
        float4 wv = *(const float4*)&W[(size_t)(row0 + lr) * I + k0 + lk];
        As[lk + 0][lr] = wv.x; As[lk + 1][lr] = wv.y;
        As[lk + 2][lr] = wv.z; As[lk + 3][lr] = wv.w;
        // X tile (natural [k][col])
        {
            int ch = k0 + xk;
            const float* src = XA; int chl = ch;
            if (XB && ch >= Dd) { src = XB; chl = ch - Dd; }
            const float* gp = &src[(size_t)chl * NN + col0 + xc];
            *(float4*)&Xs[xk][xc]     = *(const float4*)gp;
            *(float4*)&Xs[xk][xc + 4] = *(const float4*)(gp + 4);
        }
        __syncthreads();

        #pragma unroll
        for (int k = 0; k < 16; k++) {
            float4 a  = *(const float4*)&As[k][ty * 4];
            float4 x0 = *(const float4*)&Xs[k][tx * 4];
            float4 x1 = *(const float4*)&Xs[k][64 + tx * 4];
            float av[4] = {a.x, a.y, a.z, a.w};
            float xv[8] = {x0.x, x0.y, x0.z, x0.w, x1.x, x1.y, x1.z, x1.w};
            #pragma unroll
            for (int i = 0; i < 4; i++)
                #pragma unroll
                for (int j = 0; j < 8; j++)
                    acc[i][j] += av[i] * xv[j];
        }
        __syncthreads();
    }

    int O = gridDim.y * 64;
    float* Ob = Out + (size_t)b * O * NN;
    #pragma unroll
    for (int i = 0; i < 4; i++) {
        int row = row0 + ty * 4 + i;
        float bb = bias[row];
        float* p0 = &Ob[(size_t)row * NN + col0 + tx * 4];
        float* p1 = p0 + 64;
        float4 o0, o1;
        o0.x = acc[i][0] + bb; o0.y = acc[i][1] + bb;
        o0.z = acc[i][2] + bb; o0.w = acc[i][3] + bb;
        o1.x = acc[i][4] + bb; o1.y = acc[i][5] + bb;
        o1.z = acc[i][6] + bb; o1.w = acc[i][7] + bb;
        if (addOut) {
            float4 e0 = *(const float4*)p0, e1 = *(const float4*)p1;
            o0.x += e0.x; o0.y += e0.y; o0.z += e0.z; o0.w += e0.w;
            o1.x += e1.x; o1.y += e1.y; o1.z += e1.z; o1.w += e1.w;
        }
        *(float4*)p0 = o0;
        *(float4*)p1 = o1;
    }
}

// ---------------------------------------------------------------------------
// Fused flash attention (fp32, multiplicative mask, online softmax).
// Block: bh = blockIdx.y (16), n-tile of 128 rows = blockIdx.x (8).
// 256 threads. Per m-tile of 64:
//   S[n][m] phase: thread rows n=ty*8+i (8), cols m=tx*4+j (4)
//   softmax: row reductions via shfl across tx (intra half-warp);
//            m/l state in registers (replicated per half-warp)
//   O[n][d] phase: thread rows n=ty*8+i, cols d=tx*4+j
// Output staged through smem for coalesced stores.
// ---------------------------------------------------------------------------
__global__ __launch_bounds__(256) void attn_kernel(
    const float* __restrict__ Q, const float* __restrict__ K,
    const float* __restrict__ V,
    const float* __restrict__ M0, const float* __restrict__ M1,
    float* __restrict__ Xatt)
{
    extern __shared__ float sm[];
    float (*Qs)[132] = (float(*)[132])sm;                       // [d][n] 64x132
    float (*Ks)[68]  = (float(*)[68])(sm + 64 * 132);           // [d][m] 64x68
    float (*Vs)[68]  = (float(*)[68])(sm + 64 * 132 + 64 * 68); // [m][d] 64x68
    float (*Ps)[68]  = (float(*)[68])(sm + 64 * 132 + 2 * 64 * 68); // [n][m] 128x68

    int bh = blockIdx.y; int b = bh >> 2, h = bh & 3;
    int n0 = blockIdx.x * 128;
    int t  = threadIdx.x;
    int tx = t & 15, ty = t >> 4;

    const float* Qb = Q + (size_t)b * Dd * NN;
    const float* Kb = K + (size_t)b * Dd * NN;
    const float* Vb = V + (size_t)b * Dd * NN;
    const float* Mb = (b < 2) ? M0 + (size_t)b * NN * NN
                              : M1 + (size_t)(b - 2) * NN * NN;

    // Load Q tile [64 d][128 n]
    {
        int d = t >> 2, c0 = (t & 3) * 32;
        const float* gp = &Qb[(size_t)(d * 4 + h) * NN + n0 + c0];
        #pragma unroll
        for (int u = 0; u < 8; u++)
            *(float4*)&Qs[d][c0 + u * 4] = *(const float4*)(gp + u * 4);
    }

    float oacc[8][4] = {};
    float mrow[8], lrow[8];
    #pragma unroll
    for (int i = 0; i < 8; i++) { mrow[i] = -1e30f; lrow[i] = 0.f; }

    for (int m0 = 0; m0 < NN; m0 += 64) {
        __syncthreads();   // prior O-phase reads done; also covers initial Q store
        // K tile natural [d][m]; V tile transposed [m][d]
        {
            int d = t >> 2, c0 = (t & 3) * 16;
            const float* gk = &Kb[(size_t)(d * 4 + h) * NN + m0 + c0];
            const float* gv = &Vb[(size_t)(d * 4 + h) * NN + m0 + c0];
            #pragma unroll
            for (int u = 0; u < 4; u++)
                *(float4*)&Ks[d][c0 + u * 4] = *(const float4*)(gk + u * 4);
            #pragma unroll
            for (int u = 0; u < 4; u++) {
                float4 vv = *(const float4*)(gv + u * 4);
                Vs[c0 + u * 4 + 0][d] = vv.x;
                Vs[c0 + u * 4 + 1][d] = vv.y;
                Vs[c0 + u * 4 + 2][d] = vv.z;
                Vs[c0 + u * 4 + 3][d] = vv.w;
            }
        }
        __syncthreads();

        // ---- S = (Q^T K) tile: s[i][j], rows n=ty*8+i, cols m=tx*4+j ----
        float s[8][4] = {};
        #pragma unroll 8
        for (int k = 0; k < 64; k++) {
            float4 q0 = *(const float4*)&Qs[k][ty * 8];
            float4 q1 = *(const float4*)&Qs[k][ty * 8 + 4];
            float4 kk = *(const float4*)&Ks[k][tx * 4];
            float qv[8] = {q0.x, q0.y, q0.z, q0.w, q1.x, q1.y, q1.z, q1.w};
            float kv[4] = {kk.x, kk.y, kk.z, kk.w};
            #pragma unroll
            for (int i = 0; i < 8; i++)
                #pragma unroll
                for (int j = 0; j < 4; j++)
                    s[i][j] += qv[i] * kv[j];
        }

        // ---- mask + online softmax ----
        #pragma unroll
        for (int i = 0; i < 8; i++) {
            size_t n = (size_t)(n0 + ty * 8 + i);
            float4 mk = *(const float4*)&Mb[n * NN + m0 + tx * 4];
            float a0 = s[i][0] * 0.125f * mk.x;
            float a1 = s[i][1] * 0.125f * mk.y;
            float a2 = s[i][2] * 0.125f * mk.z;
            float a3 = s[i][3] * 0.125f * mk.w;
            float rm = fmaxf(fmaxf(a0, a1), fmaxf(a2, a3));
            rm = fmaxf(rm, __shfl_xor_sync(0xffffffffu, rm, 1));
            rm = fmaxf(rm, __shfl_xor_sync(0xffffffffu, rm, 2));
            rm = fmaxf(rm, __shfl_xor_sync(0xffffffffu, rm, 4));
            rm = fmaxf(rm, __shfl_xor_sync(0xffffffffu, rm, 8));
            float newm = fmaxf(mrow[i], rm);
            float p0 = __expf(a0 - newm), p1 = __expf(a1 - newm);
            float p2 = __expf(a2 - newm), p3 = __expf(a3 - newm);
            float rs = (p0 + p1) + (p2 + p3);
            rs += __shfl_xor_sync(0xffffffffu, rs, 1);
            rs += __shfl_xor_sync(0xffffffffu, rs, 2);
            rs += __shfl_xor_sync(0xffffffffu, rs, 4);
            rs += __shfl_xor_sync(0xffffffffu, rs, 8);
            float fac = __expf(mrow[i] - newm);
            mrow[i] = newm;
            lrow[i] = lrow[i] * fac + rs;
            oacc[i][0] *= fac; oacc[i][1] *= fac;
            oacc[i][2] *= fac; oacc[i][3] *= fac;
            float4 pv; pv.x = p0; pv.y = p1; pv.z = p2; pv.w = p3;
            *(float4*)&Ps[ty * 8 + i][tx * 4] = pv;
        }
        __syncthreads();

        // ---- O += P V^T: k over m (64), 4-k chunks ----
        #pragma unroll 2
        for (int k4 = 0; k4 < 64; k4 += 4) {
            float4 v0 = *(const float4*)&Vs[k4 + 0][tx * 4];
            float4 v1 = *(const float4*)&Vs[k4 + 1][tx * 4];
            float4 v2 = *(const float4*)&Vs[k4 + 2][tx * 4];
            float4 v3 = *(const float4*)&Vs[k4 + 3][tx * 4];
            #pragma unroll
            for (int i = 0; i < 8; i++) {
                float4 p = *(const float4*)&Ps[ty * 8 + i][k4];
                oacc[i][0] += p.x * v0.x; oacc[i][1] += p.x * v0.y;
                oacc[i][2] += p.x * v0.z; oacc[i][3] += p.x * v0.w;
                oacc[i][0] += p.y * v1.x; oacc[i][1] += p.y * v1.y;
                oacc[i][2] += p.y * v1.z; oacc[i][3] += p.y * v1.w;
                oacc[i][0] += p.z * v2.x; oacc[i][1] += p.z * v2.y;
                oacc[i][2] += p.z * v2.z; oacc[i][3] += p.z * v2.w;
                oacc[i][0] += p.w * v3.x; oacc[i][1] += p.w * v3.y;
                oacc[i][2] += p.w * v3.z; oacc[i][3] += p.w * v3.w;
            }
        }
    }

    // ---- normalize and write (stage through Qs for coalesced stores) ----
    __syncthreads();
    #pragma unroll
    for (int i = 0; i < 8; i++) {
        float inv = 1.0f / lrow[i];
        #pragma unroll
        for (int j = 0; j < 4; j++)
            Qs[tx * 4 + j][ty * 8 + i] = oacc[i][j] * inv;  // Obuf[d][n]
    }
    __syncthreads();
    {
        int d = t >> 2, c0 = (t & 3) * 32;
        float* op = &Xatt[(size_t)b * Dd * NN + (size_t)(d * 4 + h) * NN + n0 + c0];
        #pragma unroll
        for (int u = 0; u < 8; u++)
            *(float4*)(op + u * 4) = *(const float4*)&Qs[d][c0 + u * 4];
    }
}

// ---------------------------------------------------------------------------
// BatchNorm1d (training mode): stats over (B=4, N=1024) per channel.
// ---------------------------------------------------------------------------
__global__ __launch_bounds__(256) void bn_stats(
    const float* __restrict__ Y, const float* __restrict__ g, const float* __restrict__ beta)
{
    int c = blockIdx.x;
    int t = threadIdx.x;
    float s = 0.f, sq = 0.f;
    for (int b = 0; b < 4; b++) {
        const float* Yp = Y + (size_t)b * D2 * NN + (size_t)c * NN;
        for (int n = t; n < NN; n += 256) {
            float v = Yp[n];
            s += v; sq += v * v;
        }
    }
    __shared__ float rs[256], rq[256];
    rs[t] = s; rq[t] = sq; __syncthreads();
    #pragma unroll
    for (int st = 128; st > 0; st >>= 1) {
        if (t < st) { rs[t] += rs[t + st]; rq[t] += rq[t + st]; }
        __syncthreads();
    }
    if (t == 0) {
        float mean = rs[0] * (1.0f / 4096.0f);
        float var  = rq[0] * (1.0f / 4096.0f) - mean * mean;
        float rstd = rsqrtf(var + 1e-5f);
        float sc = g[c] * rstd;
        g_scale[c] = sc;
        g_shift[c] = beta[c] - mean * sc;
    }
}

__global__ __launch_bounds__(256) void bn_relu(float* __restrict__ Y)
{
    int i = blockIdx.x * 256 + threadIdx.x;   // 4*512*1024 total
    int c = (i >> 10) & 511;
    float v = Y[i] * g_scale[c] + g_shift[c];
    Y[i] = v > 0.f ? v : 0.f;
}

// ---------------------------------------------------------------------------
extern "C" void kernel_launch(void* const* d_in, const int* in_sizes, int n_in,
                              void* d_out, int out_size)
{
    const float* desc0 = (const float*)d_in[0];
    const float* desc1 = (const float*)d_in[1];
    const float* M0    = (const float*)d_in[2];
    const float* M1    = (const float*)d_in[3];
    const float* Wq = (const float*)d_in[4];
    const float* bq = (const float*)d_in[5];
    const float* Wk = (const float*)d_in[6];
    const float* bk = (const float*)d_in[7];
    const float* Wv = (const float*)d_in[8];
    const float* bv = (const float*)d_in[9];
    const float* Wm = (const float*)d_in[10];
    const float* bm = (const float*)d_in[11];
    const float* W1 = (const float*)d_in[12];
    const float* b1 = (const float*)d_in[13];
    const float* g1 = (const float*)d_in[14];
    const float* be1 = (const float*)d_in[15];
    const float* W2 = (const float*)d_in[16];
    const float* b2 = (const float*)d_in[17];

    float* Dsc = (float*)d_out;   // [4, 256, 1024] — doubles as the output

    float *Q, *K, *V, *Xatt, *Msg, *Y1;
    cudaGetSymbolAddress((void**)&Q,    g_Q);
    cudaGetSymbolAddress((void**)&K,    g_K);
    cudaGetSymbolAddress((void**)&V,    g_V);
    cudaGetSymbolAddress((void**)&Xatt, g_Xatt);
    cudaGetSymbolAddress((void**)&Msg,  g_Msg);
    cudaGetSymbolAddress((void**)&Y1,   g_Y1);

    static const int ATTN_SMEM = (64 * 132 + 2 * 64 * 68 + 128 * 68) * 4; // ~101 KB
    cudaFuncSetAttribute(attn_kernel, cudaFuncAttributeMaxDynamicSharedMemorySize, ATTN_SMEM);

    size_t descBytes = (size_t)2 * Dd * NN * sizeof(float);
    cudaMemcpyAsync(Dsc,               desc0, descBytes, cudaMemcpyDeviceToDevice, 0);
    cudaMemcpyAsync(Dsc + 2 * Dd * NN, desc1, descBytes, cudaMemcpyDeviceToDevice, 0);

    static const int crossFlag[LL] = {0, 1, 0, 1, 0, 1};

    for (int i = 0; i < LL; i++) {
        int xm = crossFlag[i] ? 2 : 0;
        const float* Wqi = Wq + (size_t)i * Dd * Dd;
        const float* bqi = bq + (size_t)i * Dd;
        const float* Wki = Wk + (size_t)i * Dd * Dd;
        const float* bki = bk + (size_t)i * Dd;
        const float* Wvi = Wv + (size_t)i * Dd * Dd;
        const float* bvi = bv + (size_t)i * Dd;
        const float* Wmi = Wm + (size_t)i * Dd * Dd;
        const float* bmi = bm + (size_t)i * Dd;
        const float* W1i = W1 + (size_t)i * D2 * D2;
        const float* b1i = b1 + (size_t)i * D2;
        const float* g1i = g1 + (size_t)i * D2;
        const float* be1i = be1 + (size_t)i * D2;
        const float* W2i = W2 + (size_t)i * Dd * D2;
        const float* b2i = b2 + (size_t)i * Dd;

        // Q from x, K/V from src (= x for self, swapped halves for cross)
        conv_gemm<<<dim3(8, 4, 4), 256>>>(Wqi, bqi, Dsc, nullptr, Dd, 0,  Q, 0);
        conv_gemm<<<dim3(8, 4, 4), 256>>>(Wki, bki, Dsc, nullptr, Dd, xm, K, 0);
        conv_gemm<<<dim3(8, 4, 4), 256>>>(Wvi, bvi, Dsc, nullptr, Dd, xm, V, 0);

        attn_kernel<<<dim3(8, 16), 256, ATTN_SMEM>>>(Q, K, V, M0, M1, Xatt);

        // merge conv
        conv_gemm<<<dim3(8, 4, 4), 256>>>(Wmi, bmi, Xatt, nullptr, Dd, 0, Msg, 0);

        // MLP: conv1 (concat [x; msg] along channels), BN+relu, conv2 (+residual)
        conv_gemm<<<dim3(8, 8, 4), 256>>>(W1i, b1i, Dsc, Msg, D2, 0, Y1, 0);
        bn_stats<<<D2, 256>>>(Y1, g1i, be1i);
        bn_relu<<<(B4 * D2 * NN) / 256, 256>>>(Y1);
        conv_gemm<<<dim3(8, 4, 4), 256>>>(W2i, b2i, Y1, nullptr, D2, 0, Dsc, 1);
    }
}

// round 4
// speedup vs baseline: 1.7486x; 1.2630x over previous
#include <cuda_runtime.h>
#include <cstdint>

#define B4   4      // 2*BS concatenated batch
#define Dd   256    // feature dim
#define D2   512
#define NN   1024   // keypoints
#define LL   6

// Scratch (device globals; no allocation allowed)
__device__ float g_Q[B4 * Dd * NN];
__device__ float g_K[B4 * Dd * NN];
__device__ float g_V[B4 * Dd * NN];
__device__ float g_Xatt[B4 * Dd * NN];
__device__ float g_Msg[B4 * Dd * NN];
__device__ float g_Y1[B4 * D2 * NN];
__device__ float g_scale[D2];
__device__ float g_shift[D2];

__device__ __forceinline__ uint32_t f2tf(float f) {
    uint32_t u; asm("cvt.rna.tf32.f32 %0, %1;" : "=r"(u) : "f"(f)); return u;
}
__device__ __forceinline__ void mma8(float c[4], const uint32_t a[4], const uint32_t b[2]) {
    asm volatile("mma.sync.aligned.m16n8k8.row.col.f32.tf32.tf32.f32 "
        "{%0,%1,%2,%3}, {%4,%5,%6,%7}, {%8,%9}, {%0,%1,%2,%3};"
        : "+f"(c[0]), "+f"(c[1]), "+f"(c[2]), "+f"(c[3])
        : "r"(a[0]), "r"(a[1]), "r"(a[2]), "r"(a[3]), "r"(b[0]), "r"(b[1]));
}

// ---------------------------------------------------------------------------
// tf32 GEMM core. Block tile 128(M) x 64(N), K-tile 32. 8 warps (2x4),
// warp tile 64x16. A smem [m][k] stride 36 (banks 4m+k: conflict-free frags,
// aligned uint4 STS). B smem [k][n] stride 72 (banks 8k+n: conflict-free).
// ---------------------------------------------------------------------------
template<int BNRELU, int CONCAT>
__device__ __forceinline__ void gemm_core(
    const float* __restrict__ Wp, int I,
    const float* __restrict__ XA, const float* __restrict__ XB,
    int col0, uint32_t (*As)[36], uint32_t (*Bs)[72],
    float acc[4][2][4])
{
    int t = threadIdx.x;
    int lane = t & 31;
    int w = t >> 5;
    int warp_m = (w >> 2) * 64, warp_n = (w & 3) * 16;
    int ar = t >> 1, ak = (t & 1) * 16;     // A: row, 16-k half
    int bk = t >> 3, bn = (t & 7) * 8;      // B: k row, 8-n chunk

    for (int k0 = 0; k0 < I; k0 += 32) {
        // A tile: W[row0+r][k0..k0+31], direct [m][k] with tf32 convert
        #pragma unroll
        for (int u = 0; u < 4; u++) {
            float4 wv = *(const float4*)&Wp[(size_t)ar * I + k0 + ak + u * 4];
            uint4 s;
            s.x = f2tf(wv.x); s.y = f2tf(wv.y); s.z = f2tf(wv.z); s.w = f2tf(wv.w);
            *(uint4*)&As[ar][ak + u * 4] = s;
        }
        // B tile: X[ch][n], natural [k][n]
        {
            int ch = k0 + bk;
            const float* src = XA; int chl = ch;
            if (CONCAT && ch >= 256) { src = XB; chl = ch - 256; }
            const float* gp = &src[(size_t)chl * NN + col0 + bn];
            float sc = 0.f, sh = 0.f;
            if (BNRELU) { sc = g_scale[ch]; sh = g_shift[ch]; }
            #pragma unroll
            for (int u = 0; u < 2; u++) {
                float4 xv = *(const float4*)(gp + u * 4);
                if (BNRELU) {
                    xv.x = fmaxf(fmaf(xv.x, sc, sh), 0.f);
                    xv.y = fmaxf(fmaf(xv.y, sc, sh), 0.f);
                    xv.z = fmaxf(fmaf(xv.z, sc, sh), 0.f);
                    xv.w = fmaxf(fmaf(xv.w, sc, sh), 0.f);
                }
                uint4 s;
                s.x = f2tf(xv.x); s.y = f2tf(xv.y); s.z = f2tf(xv.z); s.w = f2tf(xv.w);
                *(uint4*)&Bs[bk][bn + u * 4] = s;
            }
        }
        __syncthreads();

        #pragma unroll
        for (int ks = 0; ks < 32; ks += 8) {
            uint32_t bfr[2][2];
            #pragma unroll
            for (int nt = 0; nt < 2; nt++) {
                int n = warp_n + nt * 8 + (lane >> 2);
                bfr[nt][0] = Bs[ks + (lane & 3)][n];
                bfr[nt][1] = Bs[ks + (lane & 3) + 4][n];
            }
            #pragma unroll
            for (int mt = 0; mt < 4; mt++) {
                int m = warp_m + mt * 16 + (lane >> 2);
                uint32_t a[4];
                a[0] = As[m][ks + (lane & 3)];
                a[1] = As[m + 8][ks + (lane & 3)];
                a[2] = As[m][ks + (lane & 3) + 4];
                a[3] = As[m + 8][ks + (lane & 3) + 4];
                mma8(acc[mt][0], a, bfr[0]);
                mma8(acc[mt][1], a, bfr[1]);
            }
        }
        __syncthreads();
    }
}

__device__ __forceinline__ void gemm_epilogue(
    float acc[4][2][4], const float* __restrict__ bias,
    float* __restrict__ Ob, int row0, int col0, int addOut)
{
    int t = threadIdx.x; int lane = t & 31; int w = t >> 5;
    int warp_m = (w >> 2) * 64, warp_n = (w & 3) * 16;
    #pragma unroll
    for (int mt = 0; mt < 4; mt++) {
        #pragma unroll
        for (int half = 0; half < 2; half++) {
            int r = row0 + warp_m + mt * 16 + (lane >> 2) + half * 8;
            float bb = bias[r];
            #pragma unroll
            for (int nt = 0; nt < 2; nt++) {
                int c = col0 + warp_n + nt * 8 + 2 * (lane & 3);
                float* p = &Ob[(size_t)r * NN + c];
                float v0 = acc[mt][nt][half * 2 + 0] + bb;
                float v1 = acc[mt][nt][half * 2 + 1] + bb;
                if (addOut) { float2 e = *(const float2*)p; v0 += e.x; v1 += e.y; }
                float2 o; o.x = v0; o.y = v1;
                *(float2*)p = o;
            }
        }
    }
}

// Fused Q/K/V projection: logical rows 0-255 = Q, 256-511 = K, 512-767 = V.
__global__ __launch_bounds__(256) void qkv_mma(
    const float* __restrict__ Wq, const float* __restrict__ bq,
    const float* __restrict__ Wk, const float* __restrict__ bk,
    const float* __restrict__ Wv, const float* __restrict__ bv,
    const float* __restrict__ X, int xorMask,
    float* __restrict__ Qo, float* __restrict__ Ko, float* __restrict__ Vo)
{
    __shared__ uint32_t As[128][36];
    __shared__ uint32_t Bs[32][72];
    int b    = blockIdx.z;
    int row0 = blockIdx.y * 128;
    int col0 = blockIdx.x * 64;
    int sel  = row0 >> 8;
    int lrow0 = row0 & 255;
    const float* W; const float* bias; float* Out; int xb;
    if (sel == 0)      { W = Wq; bias = bq; Out = Qo; xb = b; }
    else if (sel == 1) { W = Wk; bias = bk; Out = Ko; xb = b ^ xorMask; }
    else               { W = Wv; bias = bv; Out = Vo; xb = b ^ xorMask; }
    const float* XA = X + (size_t)xb * Dd * NN;
    float acc[4][2][4] = {};
    gemm_core<0, 0>(W + (size_t)lrow0 * Dd, Dd, XA, nullptr, col0, As, Bs, acc);
    gemm_epilogue(acc, bias, Out + (size_t)b * Dd * NN, lrow0, col0, 0);
}

template<int BNRELU, int CONCAT>
__global__ __launch_bounds__(256) void conv_mma(
    const float* __restrict__ W, const float* __restrict__ bias,
    const float* __restrict__ X, const float* __restrict__ X2,
    int I, float* __restrict__ Out, int O, int addOut)
{
    __shared__ uint32_t As[128][36];
    __shared__ uint32_t Bs[32][72];
    int b    = blockIdx.z;
    int row0 = blockIdx.y * 128;
    int col0 = blockIdx.x * 64;
    const float* XA = X + (size_t)b * (CONCAT ? 256 : I) * NN;
    const float* XB = CONCAT ? X2 + (size_t)b * 256 * NN : nullptr;
    float acc[4][2][4] = {};
    gemm_core<BNRELU, CONCAT>(W + (size_t)row0 * I, I, XA, XB, col0, As, Bs, acc);
    gemm_epilogue(acc, bias, Out + (size_t)b * O * NN, row0, col0, addOut);
}

// ---------------------------------------------------------------------------
// Fused flash attention (fp32, multiplicative mask, online softmax).
// Br=64 rows x Bc=64 cols, 256 threads, grid (16 n-tiles, 16 bh).
// Per-thread: 4 rows (ty=t>>4) x 4 cols (tx=t&15); row state in registers,
// reductions via shfl across the 16 tx lanes.
// ---------------------------------------------------------------------------
__global__ __launch_bounds__(256) void attn_kernel(
    const float* __restrict__ Q, const float* __restrict__ K,
    const float* __restrict__ V,
    const float* __restrict__ M0, const float* __restrict__ M1,
    float* __restrict__ Xatt)
{
    extern __shared__ float sm[];
    float (*Qs)[68] = (float(*)[68])sm;                      // [d][n] 64x68
    float (*Ks)[68] = (float(*)[68])(sm + 64 * 68);          // [d][m]
    float (*Vs)[68] = (float(*)[68])(sm + 2 * 64 * 68);      // [m][d]
    float (*Ps)[68] = (float(*)[68])(sm + 3 * 64 * 68);      // [n][m]

    int bh = blockIdx.y; int b = bh >> 2, h = bh & 3;
    int n0 = blockIdx.x * 64;
    int t  = threadIdx.x;
    int tx = t & 15, ty = t >> 4;

    const float* Qb = Q + (size_t)b * Dd * NN;
    const float* Kb = K + (size_t)b * Dd * NN;
    const float* Vb = V + (size_t)b * Dd * NN;
    const float* Mb = (b < 2) ? M0 + (size_t)b * NN * NN
                              : M1 + (size_t)(b - 2) * NN * NN;

    // Load Q tile [64 d][64 n]
    {
        int d = t >> 2, c0 = (t & 3) * 16;
        const float* gp = &Qb[(size_t)(d * 4 + h) * NN + n0 + c0];
        #pragma unroll
        for (int u = 0; u < 4; u++)
            *(float4*)&Qs[d][c0 + u * 4] = *(const float4*)(gp + u * 4);
    }

    float oacc[4][4] = {};
    float mrow[4], lrow[4];
    #pragma unroll
    for (int i = 0; i < 4; i++) { mrow[i] = -1e30f; lrow[i] = 0.f; }

    for (int m0 = 0; m0 < NN; m0 += 64) {
        __syncthreads();   // prior O-phase reads done (also covers Q store)
        {
            int d = t >> 2, c0 = (t & 3) * 16;
            const float* gk = &Kb[(size_t)(d * 4 + h) * NN + m0 + c0];
            const float* gv = &Vb[(size_t)(d * 4 + h) * NN + m0 + c0];
            #pragma unroll
            for (int u = 0; u < 4; u++)
                *(float4*)&Ks[d][c0 + u * 4] = *(const float4*)(gk + u * 4);
            #pragma unroll
            for (int u = 0; u < 4; u++) {
                float4 vv = *(const float4*)(gv + u * 4);
                Vs[c0 + u * 4 + 0][d] = vv.x;
                Vs[c0 + u * 4 + 1][d] = vv.y;
                Vs[c0 + u * 4 + 2][d] = vv.z;
                Vs[c0 + u * 4 + 3][d] = vv.w;
            }
        }
        __syncthreads();

        // S tile: rows n=ty*4+i, cols m=tx*4+j
        float s[4][4] = {};
        #pragma unroll 8
        for (int k = 0; k < 64; k++) {
            float4 q = *(const float4*)&Qs[k][ty * 4];
            float4 kk = *(const float4*)&Ks[k][tx * 4];
            float qv[4] = {q.x, q.y, q.z, q.w};
            float kv[4] = {kk.x, kk.y, kk.z, kk.w};
            #pragma unroll
            for (int i = 0; i < 4; i++)
                #pragma unroll
                for (int j = 0; j < 4; j++)
                    s[i][j] += qv[i] * kv[j];
        }

        // mask + online softmax
        #pragma unroll
        for (int i = 0; i < 4; i++) {
            size_t n = (size_t)(n0 + ty * 4 + i);
            float4 mk = *(const float4*)&Mb[n * NN + m0 + tx * 4];
            float a0 = s[i][0] * 0.125f * mk.x;
            float a1 = s[i][1] * 0.125f * mk.y;
            float a2 = s[i][2] * 0.125f * mk.z;
            float a3 = s[i][3] * 0.125f * mk.w;
            float rm = fmaxf(fmaxf(a0, a1), fmaxf(a2, a3));
            rm = fmaxf(rm, __shfl_xor_sync(0xffffffffu, rm, 1));
            rm = fmaxf(rm, __shfl_xor_sync(0xffffffffu, rm, 2));
            rm = fmaxf(rm, __shfl_xor_sync(0xffffffffu, rm, 4));
            rm = fmaxf(rm, __shfl_xor_sync(0xffffffffu, rm, 8));
            float newm = fmaxf(mrow[i], rm);
            float p0 = __expf(a0 - newm), p1 = __expf(a1 - newm);
            float p2 = __expf(a2 - newm), p3 = __expf(a3 - newm);
            float rs = (p0 + p1) + (p2 + p3);
            rs += __shfl_xor_sync(0xffffffffu, rs, 1);
            rs += __shfl_xor_sync(0xffffffffu, rs, 2);
            rs += __shfl_xor_sync(0xffffffffu, rs, 4);
            rs += __shfl_xor_sync(0xffffffffu, rs, 8);
            float fac = __expf(mrow[i] - newm);
            mrow[i] = newm;
            lrow[i] = lrow[i] * fac + rs;
            oacc[i][0] *= fac; oacc[i][1] *= fac;
            oacc[i][2] *= fac; oacc[i][3] *= fac;
            float4 pv; pv.x = p0; pv.y = p1; pv.z = p2; pv.w = p3;
            *(float4*)&Ps[ty * 4 + i][tx * 4] = pv;
        }
        __syncthreads();

        // O += P V^T
        #pragma unroll 4
        for (int k4 = 0; k4 < 64; k4 += 4) {
            float4 v0 = *(const float4*)&Vs[k4 + 0][tx * 4];
            float4 v1 = *(const float4*)&Vs[k4 + 1][tx * 4];
            float4 v2 = *(const float4*)&Vs[k4 + 2][tx * 4];
            float4 v3 = *(const float4*)&Vs[k4 + 3][tx * 4];
            #pragma unroll
            for (int i = 0; i < 4; i++) {
                float4 p = *(const float4*)&Ps[ty * 4 + i][k4];
                oacc[i][0] += p.x * v0.x; oacc[i][1] += p.x * v0.y;
                oacc[i][2] += p.x * v0.z; oacc[i][3] += p.x * v0.w;
                oacc[i][0] += p.y * v1.x; oacc[i][1] += p.y * v1.y;
                oacc[i][2] += p.y * v1.z; oacc[i][3] += p.y * v1.w;
                oacc[i][0] += p.z * v2.x; oacc[i][1] += p.z * v2.y;
                oacc[i][2] += p.z * v2.z; oacc[i][3] += p.z * v2.w;
                oacc[i][0] += p.w * v3.x; oacc[i][1] += p.w * v3.y;
                oacc[i][2] += p.w * v3.z; oacc[i][3] += p.w * v3.w;
            }
        }
    }

    // normalize, stage through Qs ([d][n]), coalesced store
    __syncthreads();
    #pragma unroll
    for (int i = 0; i < 4; i++) {
        float inv = 1.0f / lrow[i];
        #pragma unroll
        for (int j = 0; j < 4; j++)
            Qs[tx * 4 + j][ty * 4 + i] = oacc[i][j] * inv;
    }
    __syncthreads();
    {
        int d = t >> 2, c0 = (t & 3) * 16;
        float* op = &Xatt[(size_t)b * Dd * NN + (size_t)(d * 4 + h) * NN + n0 + c0];
        #pragma unroll
        for (int u = 0; u < 4; u++)
            *(float4*)(op + u * 4) = *(const float4*)&Qs[d][c0 + u * 4];
    }
}

// ---------------------------------------------------------------------------
// BatchNorm1d stats (training mode): over (B=4, N=1024) per channel.
// ---------------------------------------------------------------------------
__global__ __launch_bounds__(256) void bn_stats(
    const float* __restrict__ Y, const float* __restrict__ g, const float* __restrict__ beta)
{
    int c = blockIdx.x;
    int t = threadIdx.x;
    float s = 0.f, sq = 0.f;
    for (int b = 0; b < 4; b++) {
        const float* Yp = Y + (size_t)b * D2 * NN + (size_t)c * NN;
        for (int n = t; n < NN; n += 256) {
            float v = Yp[n];
            s += v; sq += v * v;
        }
    }
    __shared__ float rs[256], rq[256];
    rs[t] = s; rq[t] = sq; __syncthreads();
    #pragma unroll
    for (int st = 128; st > 0; st >>= 1) {
        if (t < st) { rs[t] += rs[t + st]; rq[t] += rq[t + st]; }
        __syncthreads();
    }
    if (t == 0) {
        float mean = rs[0] * (1.0f / 4096.0f);
        float var  = rq[0] * (1.0f / 4096.0f) - mean * mean;
        float rstd = rsqrtf(var + 1e-5f);
        float sc = g[c] * rstd;
        g_scale[c] = sc;
        g_shift[c] = beta[c] - mean * sc;
    }
}

// ---------------------------------------------------------------------------
extern "C" void kernel_launch(void* const* d_in, const int* in_sizes, int n_in,
                              void* d_out, int out_size)
{
    const float* desc0 = (const float*)d_in[0];
    const float* desc1 = (const float*)d_in[1];
    const float* M0    = (const float*)d_in[2];
    const float* M1    = (const float*)d_in[3];
    const float* Wq = (const float*)d_in[4];
    const float* bq = (const float*)d_in[5];
    const float* Wk = (const float*)d_in[6];
    const float* bk = (const float*)d_in[7];
    const float* Wv = (const float*)d_in[8];
    const float* bv = (const float*)d_in[9];
    const float* Wm = (const float*)d_in[10];
    const float* bm = (const float*)d_in[11];
    const float* W1 = (const float*)d_in[12];
    const float* b1 = (const float*)d_in[13];
    const float* g1 = (const float*)d_in[14];
    const float* be1 = (const float*)d_in[15];
    const float* W2 = (const float*)d_in[16];
    const float* b2 = (const float*)d_in[17];

    float* Dsc = (float*)d_out;   // [4, 256, 1024] — doubles as the output

    float *Q, *K, *V, *Xatt, *Msg, *Y1;
    cudaGetSymbolAddress((void**)&Q,    g_Q);
    cudaGetSymbolAddress((void**)&K,    g_K);
    cudaGetSymbolAddress((void**)&V,    g_V);
    cudaGetSymbolAddress((void**)&Xatt, g_Xatt);
    cudaGetSymbolAddress((void**)&Msg,  g_Msg);
    cudaGetSymbolAddress((void**)&Y1,   g_Y1);

    static const int ATTN_SMEM = 4 * 64 * 68 * 4;   // 69632 B
    cudaFuncSetAttribute(attn_kernel, cudaFuncAttributeMaxDynamicSharedMemorySize, ATTN_SMEM);

    size_t descBytes = (size_t)2 * Dd * NN * sizeof(float);
    cudaMemcpyAsync(Dsc,               desc0, descBytes, cudaMemcpyDeviceToDevice, 0);
    cudaMemcpyAsync(Dsc + 2 * Dd * NN, desc1, descBytes, cudaMemcpyDeviceToDevice, 0);

    static const int crossFlag[LL] = {0, 1, 0, 1, 0, 1};

    for (int i = 0; i < LL; i++) {
        int xm = crossFlag[i] ? 2 : 0;
        const float* Wqi = Wq + (size_t)i * Dd * Dd;
        const float* bqi = bq + (size_t)i * Dd;
        const float* Wki = Wk + (size_t)i * Dd * Dd;
        const float* bki = bk + (size_t)i * Dd;
        const float* Wvi = Wv + (size_t)i * Dd * Dd;
        const float* bvi = bv + (size_t)i * Dd;
        const float* Wmi = Wm + (size_t)i * Dd * Dd;
        const float* bmi = bm + (size_t)i * Dd;
        const float* W1i = W1 + (size_t)i * D2 * D2;
        const float* b1i = b1 + (size_t)i * D2;
        const float* g1i = g1 + (size_t)i * D2;
        const float* be1i = be1 + (size_t)i * D2;
        const float* W2i = W2 + (size_t)i * Dd * D2;
        const float* b2i = b2 + (size_t)i * Dd;

        // Fused Q/K/V projections (K/V read swapped halves for cross layers)
        qkv_mma<<<dim3(16, 6, 4), 256>>>(Wqi, bqi, Wki, bki, Wvi, bvi,
                                         Dsc, xm, Q, K, V);

        attn_kernel<<<dim3(16, 16), 256, ATTN_SMEM>>>(Q, K, V, M0, M1, Xatt);

        // merge conv
        conv_mma<0, 0><<<dim3(16, 2, 4), 256>>>(Wmi, bmi, Xatt, nullptr, Dd, Msg, Dd, 0);

        // MLP: conv1 (concat [x; msg]), BN stats, conv2 with fused BN+ReLU on load (+residual)
        conv_mma<0, 1><<<dim3(16, 4, 4), 256>>>(W1i, b1i, Dsc, Msg, D2, Y1, D2, 0);
        bn_stats<<<D2, 256>>>(Y1, g1i, be1i);
        conv_mma<1, 0><<<dim3(16, 2, 4), 256>>>(W2i, b2i, Y1, nullptr, D2, Dsc, Dd, 1);
    }
}

// round 5
// speedup vs baseline: 2.2479x; 1.2855x over previous
#include <cuda_runtime.h>
#include <cstdint>

#define B4   4      // 2*BS concatenated batch
#define Dd   256    // feature dim
#define D2   512
#define NN   1024   // keypoints
#define LL   6

// Scratch (device globals; no allocation allowed)
__device__ float g_Q[B4 * Dd * NN];
__device__ float g_K[B4 * Dd * NN];
__device__ float g_V[B4 * Dd * NN];
__device__ float g_Xatt[B4 * Dd * NN];
__device__ float g_Msg[B4 * Dd * NN];
__device__ float g_Y1[B4 * D2 * NN];
__device__ float g_scale[D2];
__device__ float g_shift[D2];

__device__ __forceinline__ uint32_t f2tf(float f) {
    uint32_t u; asm("cvt.rna.tf32.f32 %0, %1;" : "=r"(u) : "f"(f)); return u;
}
__device__ __forceinline__ void mma8(float c[4], const uint32_t a[4], const uint32_t b[2]) {
    asm volatile("mma.sync.aligned.m16n8k8.row.col.f32.tf32.tf32.f32 "
        "{%0,%1,%2,%3}, {%4,%5,%6,%7}, {%8,%9}, {%0,%1,%2,%3};"
        : "+f"(c[0]), "+f"(c[1]), "+f"(c[2]), "+f"(c[3])
        : "r"(a[0]), "r"(a[1]), "r"(a[2]), "r"(a[3]), "r"(b[0]), "r"(b[1]));
}

// ---------------------------------------------------------------------------
// tf32 GEMM core, double-buffered. Block tile 128(M) x 64(N), K-tile 32.
// 8 warps (2x4), warp tile 64x16. A smem [m][k] stride 36, B smem [k][n]
// stride 72 (both conflict-free for fragment LDS).
// ---------------------------------------------------------------------------
template<int BNRELU, int CONCAT>
__device__ __forceinline__ void gemm_core(
    const float* __restrict__ Wp, int I,
    const float* __restrict__ XA, const float* __restrict__ XB,
    int col0, uint32_t (*As)[128][36], uint32_t (*Bs)[32][72],
    float acc[4][2][4])
{
    int t = threadIdx.x;
    int lane = t & 31;
    int w = t >> 5;
    int warp_m = (w >> 2) * 64, warp_n = (w & 3) * 16;
    int ar = t >> 1, ak = (t & 1) * 16;     // A: row, 16-k half
    int bk = t >> 3, bn = (t & 7) * 8;      // B: k row, 8-n chunk

    int nk = I >> 5;
    float4 aReg[4];
    float4 bReg[2];
    float bSc = 0.f, bSh = 0.f;

    // --- tile-load helpers (inlined) ---
    #define LOAD_TILE(K0)                                                       \
    {                                                                           \
        int k0 = (K0);                                                          \
        _Pragma("unroll")                                                       \
        for (int u = 0; u < 4; u++)                                             \
            aReg[u] = *(const float4*)&Wp[(size_t)ar * I + k0 + ak + u * 4];    \
        int ch = k0 + bk;                                                       \
        const float* src = XA; int chl = ch;                                    \
        if (CONCAT && ch >= 256) { src = XB; chl = ch - 256; }                  \
        const float* gp = &src[(size_t)chl * NN + col0 + bn];                   \
        if (BNRELU) { bSc = g_scale[ch]; bSh = g_shift[ch]; }                   \
        bReg[0] = *(const float4*)gp;                                           \
        bReg[1] = *(const float4*)(gp + 4);                                     \
    }
    #define STORE_TILE(BUF)                                                     \
    {                                                                           \
        _Pragma("unroll")                                                       \
        for (int u = 0; u < 4; u++) {                                           \
            uint4 s;                                                            \
            s.x = f2tf(aReg[u].x); s.y = f2tf(aReg[u].y);                       \
            s.z = f2tf(aReg[u].z); s.w = f2tf(aReg[u].w);                       \
            *(uint4*)&As[BUF][ar][ak + u * 4] = s;                              \
        }                                                                       \
        _Pragma("unroll")                                                       \
        for (int u = 0; u < 2; u++) {                                           \
            float4 xv = bReg[u];                                                \
            if (BNRELU) {                                                       \
                xv.x = fmaxf(fmaf(xv.x, bSc, bSh), 0.f);                        \
                xv.y = fmaxf(fmaf(xv.y, bSc, bSh), 0.f);                        \
                xv.z = fmaxf(fmaf(xv.z, bSc, bSh), 0.f);                        \
                xv.w = fmaxf(fmaf(xv.w, bSc, bSh), 0.f);                        \
            }                                                                   \
            uint4 s;                                                            \
            s.x = f2tf(xv.x); s.y = f2tf(xv.y);                                 \
            s.z = f2tf(xv.z); s.w = f2tf(xv.w);                                 \
            *(uint4*)&Bs[BUF][bk][bn + u * 4] = s;                              \
        }                                                                       \
    }

    LOAD_TILE(0);
    STORE_TILE(0);
    __syncthreads();

    for (int kt = 0; kt < nk; kt++) {
        int cur = kt & 1;
        if (kt + 1 < nk) LOAD_TILE((kt + 1) << 5);

        #pragma unroll
        for (int ks = 0; ks < 32; ks += 8) {
            uint32_t bfr[2][2];
            #pragma unroll
            for (int nt = 0; nt < 2; nt++) {
                int n = warp_n + nt * 8 + (lane >> 2);
                bfr[nt][0] = Bs[cur][ks + (lane & 3)][n];
                bfr[nt][1] = Bs[cur][ks + (lane & 3) + 4][n];
            }
            #pragma unroll
            for (int mt = 0; mt < 4; mt++) {
                int m = warp_m + mt * 16 + (lane >> 2);
                uint32_t a[4];
                a[0] = As[cur][m][ks + (lane & 3)];
                a[1] = As[cur][m + 8][ks + (lane & 3)];
                a[2] = As[cur][m][ks + (lane & 3) + 4];
                a[3] = As[cur][m + 8][ks + (lane & 3) + 4];
                mma8(acc[mt][0], a, bfr[0]);
                mma8(acc[mt][1], a, bfr[1]);
            }
        }
        if (kt + 1 < nk) STORE_TILE(cur ^ 1);
        __syncthreads();
    }
    #undef LOAD_TILE
    #undef STORE_TILE
}

__device__ __forceinline__ void gemm_epilogue(
    float acc[4][2][4], const float* __restrict__ bias,
    float* __restrict__ Ob, int row0, int col0, int addOut)
{
    int t = threadIdx.x; int lane = t & 31; int w = t >> 5;
    int warp_m = (w >> 2) * 64, warp_n = (w & 3) * 16;
    #pragma unroll
    for (int mt = 0; mt < 4; mt++) {
        #pragma unroll
        for (int half = 0; half < 2; half++) {
            int r = row0 + warp_m + mt * 16 + (lane >> 2) + half * 8;
            float bb = bias[r];
            #pragma unroll
            for (int nt = 0; nt < 2; nt++) {
                int c = col0 + warp_n + nt * 8 + 2 * (lane & 3);
                float* p = &Ob[(size_t)r * NN + c];
                float v0 = acc[mt][nt][half * 2 + 0] + bb;
                float v1 = acc[mt][nt][half * 2 + 1] + bb;
                if (addOut) { float2 e = *(const float2*)p; v0 += e.x; v1 += e.y; }
                float2 o; o.x = v0; o.y = v1;
                *(float2*)p = o;
            }
        }
    }
}

// Fused Q/K/V projection: logical rows 0-255 = Q, 256-511 = K, 512-767 = V.
__global__ __launch_bounds__(256) void qkv_mma(
    const float* __restrict__ Wq, const float* __restrict__ bq,
    const float* __restrict__ Wk, const float* __restrict__ bk,
    const float* __restrict__ Wv, const float* __restrict__ bv,
    const float* __restrict__ X, int xorMask,
    float* __restrict__ Qo, float* __restrict__ Ko, float* __restrict__ Vo)
{
    __shared__ uint32_t As[2][128][36];
    __shared__ uint32_t Bs[2][32][72];
    int b    = blockIdx.z;
    int row0 = blockIdx.y * 128;
    int col0 = blockIdx.x * 64;
    int sel  = row0 >> 8;
    int lrow0 = row0 & 255;
    const float* W; const float* bias; float* Out; int xb;
    if (sel == 0)      { W = Wq; bias = bq; Out = Qo; xb = b; }
    else if (sel == 1) { W = Wk; bias = bk; Out = Ko; xb = b ^ xorMask; }
    else               { W = Wv; bias = bv; Out = Vo; xb = b ^ xorMask; }
    const float* XA = X + (size_t)xb * Dd * NN;
    float acc[4][2][4] = {};
    gemm_core<0, 0>(W + (size_t)lrow0 * Dd, Dd, XA, nullptr, col0, As, Bs, acc);
    gemm_epilogue(acc, bias, Out + (size_t)b * Dd * NN, lrow0, col0, 0);
}

template<int BNRELU, int CONCAT>
__global__ __launch_bounds__(256) void conv_mma(
    const float* __restrict__ W, const float* __restrict__ bias,
    const float* __restrict__ X, const float* __restrict__ X2,
    int I, float* __restrict__ Out, int O, int addOut)
{
    __shared__ uint32_t As[2][128][36];
    __shared__ uint32_t Bs[2][32][72];
    int b    = blockIdx.z;
    int row0 = blockIdx.y * 128;
    int col0 = blockIdx.x * 64;
    const float* XA = X + (size_t)b * (CONCAT ? 256 : I) * NN;
    const float* XB = CONCAT ? X2 + (size_t)b * 256 * NN : nullptr;
    float acc[4][2][4] = {};
    gemm_core<BNRELU, CONCAT>(W + (size_t)row0 * I, I, XA, XB, col0, As, Bs, acc);
    gemm_epilogue(acc, bias, Out + (size_t)b * O * NN, row0, col0, addOut);
}

// ---------------------------------------------------------------------------
// Flash attention with tf32 mma for S = Q^T K and O = P V.
// Block: 64 q-rows x 64 kv-cols, 128 threads (4 warps). Warp w owns rows
// [16w, 16w+16) and ALL 64 cols -> softmax row reductions stay inside a
// lane quad (shfl xor 1,2). Online-softmax state in registers.
// Smem: Qs[n][d] s68 tf32 (A-frags), Ks[d][m] s72 (B), Vs[m][d] s72 (B),
// Ps[n][m] s68 tf32 (A) / reused as fp32 [d][n] staging for output.
// ---------------------------------------------------------------------------
__global__ __launch_bounds__(128) void attn_mma(
    const float* __restrict__ Q, const float* __restrict__ K,
    const float* __restrict__ V,
    const float* __restrict__ M0, const float* __restrict__ M1,
    float* __restrict__ Xatt)
{
    extern __shared__ uint32_t smu[];
    uint32_t (*Qs)[68] = (uint32_t(*)[68])smu;                       // [n][d]
    uint32_t (*Ks)[72] = (uint32_t(*)[72])(smu + 64 * 68);           // [d][m]
    uint32_t (*Vs)[72] = (uint32_t(*)[72])(smu + 64 * 68 + 64 * 72); // [m][d]
    uint32_t (*Ps)[68] = (uint32_t(*)[68])(smu + 64 * 68 + 2 * 64 * 72); // [n][m]
    float    (*Osf)[68] = (float(*)[68])Ps;                          // staging alias

    int bh = blockIdx.y; int b = bh >> 2, h = bh & 3;
    int n0 = blockIdx.x * 64;
    int t = threadIdx.x;
    int lane = t & 31, w = t >> 5;
    int g = lane >> 2, q = lane & 3;
    int rowb = w * 16;

    const float* Qb = Q + (size_t)b * Dd * NN;
    const float* Kb = K + (size_t)b * Dd * NN;
    const float* Vb = V + (size_t)b * Dd * NN;
    const float* Mb = (b < 2) ? M0 + (size_t)b * NN * NN
                              : M1 + (size_t)(b - 2) * NN * NN;

    // Load Q tile -> Qs[n][d], tf32, pre-scaled by 1/8
    {
        int d = t >> 1, nc = (t & 1) * 32;
        const float* gp = &Qb[(size_t)(d * 4 + h) * NN + n0 + nc];
        #pragma unroll
        for (int u = 0; u < 8; u++) {
            float4 v = *(const float4*)(gp + u * 4);
            Qs[nc + u * 4 + 0][d] = f2tf(v.x * 0.125f);
            Qs[nc + u * 4 + 1][d] = f2tf(v.y * 0.125f);
            Qs[nc + u * 4 + 2][d] = f2tf(v.z * 0.125f);
            Qs[nc + u * 4 + 3][d] = f2tf(v.w * 0.125f);
        }
    }

    float oacc[8][4] = {};
    float m0r = -1e30f, m1r = -1e30f, l0 = 0.f, l1 = 0.f;
    int r0g = n0 + rowb + g;           // global q-row for c0/c1
    int r1g = r0g + 8;                 // global q-row for c2/c3

    for (int mt = 0; mt < NN; mt += 64) {
        __syncthreads();   // prior PV reads of Ks/Vs/Ps done (and Qs stores, iter 0)
        // Load K,V tiles
        {
            int d = t >> 1, mc = (t & 1) * 32;
            const float* gk = &Kb[(size_t)(d * 4 + h) * NN + mt + mc];
            const float* gv = &Vb[(size_t)(d * 4 + h) * NN + mt + mc];
            #pragma unroll
            for (int u = 0; u < 8; u++) {
                float4 kv = *(const float4*)(gk + u * 4);
                uint4 s;
                s.x = f2tf(kv.x); s.y = f2tf(kv.y); s.z = f2tf(kv.z); s.w = f2tf(kv.w);
                *(uint4*)&Ks[d][mc + u * 4] = s;
            }
            #pragma unroll
            for (int u = 0; u < 8; u++) {
                float4 vv = *(const float4*)(gv + u * 4);
                Vs[mc + u * 4 + 0][d] = f2tf(vv.x);
                Vs[mc + u * 4 + 1][d] = f2tf(vv.y);
                Vs[mc + u * 4 + 2][d] = f2tf(vv.z);
                Vs[mc + u * 4 + 3][d] = f2tf(vv.w);
            }
        }
        __syncthreads();

        // ---- S = Q^T K (rows rowb..rowb+15, cols 0..63) ----
        float sacc[8][4] = {};
        #pragma unroll
        for (int ks = 0; ks < 8; ks++) {
            int kk = ks * 8;
            uint32_t a[4];
            a[0] = Qs[rowb + g][kk + q];
            a[1] = Qs[rowb + g + 8][kk + q];
            a[2] = Qs[rowb + g][kk + q + 4];
            a[3] = Qs[rowb + g + 8][kk + q + 4];
            #pragma unroll
            for (int nf = 0; nf < 8; nf++) {
                uint32_t bb[2];
                bb[0] = Ks[kk + q][nf * 8 + g];
                bb[1] = Ks[kk + q + 4][nf * 8 + g];
                mma8(sacc[nf], a, bb);
            }
        }

        // ---- mask + online softmax ----
        const float* mr0 = Mb + (size_t)r0g * NN + mt;
        const float* mr1 = Mb + (size_t)r1g * NN + mt;
        float v0[16], v1[16];
        float rm0 = -1e30f, rm1 = -1e30f;
        #pragma unroll
        for (int nf = 0; nf < 8; nf++) {
            int c = nf * 8 + 2 * q;
            float2 k0v = *(const float2*)&mr0[c];
            float2 k1v = *(const float2*)&mr1[c];
            v0[2 * nf]     = sacc[nf][0] * k0v.x;
            v0[2 * nf + 1] = sacc[nf][1] * k0v.y;
            v1[2 * nf]     = sacc[nf][2] * k1v.x;
            v1[2 * nf + 1] = sacc[nf][3] * k1v.y;
            rm0 = fmaxf(rm0, fmaxf(v0[2 * nf], v0[2 * nf + 1]));
            rm1 = fmaxf(rm1, fmaxf(v1[2 * nf], v1[2 * nf + 1]));
        }
        rm0 = fmaxf(rm0, __shfl_xor_sync(0xffffffffu, rm0, 1));
        rm0 = fmaxf(rm0, __shfl_xor_sync(0xffffffffu, rm0, 2));
        rm1 = fmaxf(rm1, __shfl_xor_sync(0xffffffffu, rm1, 1));
        rm1 = fmaxf(rm1, __shfl_xor_sync(0xffffffffu, rm1, 2));
        float nm0 = fmaxf(m0r, rm0), nm1 = fmaxf(m1r, rm1);
        float rs0 = 0.f, rs1 = 0.f;
        #pragma unroll
        for (int i = 0; i < 16; i++) {
            v0[i] = __expf(v0[i] - nm0); rs0 += v0[i];
            v1[i] = __expf(v1[i] - nm1); rs1 += v1[i];
        }
        rs0 += __shfl_xor_sync(0xffffffffu, rs0, 1);
        rs0 += __shfl_xor_sync(0xffffffffu, rs0, 2);
        rs1 += __shfl_xor_sync(0xffffffffu, rs1, 1);
        rs1 += __shfl_xor_sync(0xffffffffu, rs1, 2);
        float f0 = __expf(m0r - nm0), f1 = __expf(m1r - nm1);
        m0r = nm0; m1r = nm1;
        l0 = l0 * f0 + rs0;
        l1 = l1 * f1 + rs1;
        #pragma unroll
        for (int df = 0; df < 8; df++) {
            oacc[df][0] *= f0; oacc[df][1] *= f0;
            oacc[df][2] *= f1; oacc[df][3] *= f1;
        }
        // store P (tf32) to Ps[n][m]
        #pragma unroll
        for (int nf = 0; nf < 8; nf++) {
            uint2 p0, p1;
            p0.x = f2tf(v0[2 * nf]); p0.y = f2tf(v0[2 * nf + 1]);
            p1.x = f2tf(v1[2 * nf]); p1.y = f2tf(v1[2 * nf + 1]);
            *(uint2*)&Ps[rowb + g][nf * 8 + 2 * q] = p0;
            *(uint2*)&Ps[rowb + g + 8][nf * 8 + 2 * q] = p1;
        }
        __syncthreads();

        // ---- O += P V ----
        #pragma unroll
        for (int ks = 0; ks < 8; ks++) {
            int kk = ks * 8;
            uint32_t a[4];
            a[0] = Ps[rowb + g][kk + q];
            a[1] = Ps[rowb + g + 8][kk + q];
            a[2] = Ps[rowb + g][kk + q + 4];
            a[3] = Ps[rowb + g + 8][kk + q + 4];
            #pragma unroll
            for (int df = 0; df < 8; df++) {
                uint32_t bb[2];
                bb[0] = Vs[kk + q][df * 8 + g];
                bb[1] = Vs[kk + q + 4][df * 8 + g];
                mma8(oacc[df], a, bb);
            }
        }
    }

    // ---- normalize, stage [d][n], coalesced store ----
    __syncthreads();
    {
        float i0 = 1.0f / l0, i1 = 1.0f / l1;
        #pragma unroll
        for (int df = 0; df < 8; df++) {
            int d0 = df * 8 + 2 * q;
            Osf[d0][rowb + g]         = oacc[df][0] * i0;
            Osf[d0 + 1][rowb + g]     = oacc[df][1] * i0;
            Osf[d0][rowb + g + 8]     = oacc[df][2] * i1;
            Osf[d0 + 1][rowb + g + 8] = oacc[df][3] * i1;
        }
    }
    __syncthreads();
    {
        int d = t >> 1, nc = (t & 1) * 32;
        float* op = &Xatt[(size_t)b * Dd * NN + (size_t)(d * 4 + h) * NN + n0 + nc];
        #pragma unroll
        for (int u = 0; u < 8; u++)
            *(float4*)(op + u * 4) = *(const float4*)&Osf[d][nc + u * 4];
    }
}

// ---------------------------------------------------------------------------
// BatchNorm1d stats (training mode): over (B=4, N=1024) per channel.
// ---------------------------------------------------------------------------
__global__ __launch_bounds__(256) void bn_stats(
    const float* __restrict__ Y, const float* __restrict__ g, const float* __restrict__ beta)
{
    int c = blockIdx.x;
    int t = threadIdx.x;
    float s = 0.f, sq = 0.f;
    for (int b = 0; b < 4; b++) {
        const float* Yp = Y + (size_t)b * D2 * NN + (size_t)c * NN;
        for (int n = t; n < NN; n += 256) {
            float v = Yp[n];
            s += v; sq += v * v;
        }
    }
    __shared__ float rs[256], rq[256];
    rs[t] = s; rq[t] = sq; __syncthreads();
    #pragma unroll
    for (int st = 128; st > 0; st >>= 1) {
        if (t < st) { rs[t] += rs[t + st]; rq[t] += rq[t + st]; }
        __syncthreads();
    }
    if (t == 0) {
        float mean = rs[0] * (1.0f / 4096.0f);
        float var  = rq[0] * (1.0f / 4096.0f) - mean * mean;
        float rstd = rsqrtf(var + 1e-5f);
        float sc = g[c] * rstd;
        g_scale[c] = sc;
        g_shift[c] = beta[c] - mean * sc;
    }
}

// ---------------------------------------------------------------------------
extern "C" void kernel_launch(void* const* d_in, const int* in_sizes, int n_in,
                              void* d_out, int out_size)
{
    const float* desc0 = (const float*)d_in[0];
    const float* desc1 = (const float*)d_in[1];
    const float* M0    = (const float*)d_in[2];
    const float* M1    = (const float*)d_in[3];
    const float* Wq = (const float*)d_in[4];
    const float* bq = (const float*)d_in[5];
    const float* Wk = (const float*)d_in[6];
    const float* bk = (const float*)d_in[7];
    const float* Wv = (const float*)d_in[8];
    const float* bv = (const float*)d_in[9];
    const float* Wm = (const float*)d_in[10];
    const float* bm = (const float*)d_in[11];
    const float* W1 = (const float*)d_in[12];
    const float* b1 = (const float*)d_in[13];
    const float* g1 = (const float*)d_in[14];
    const float* be1 = (const float*)d_in[15];
    const float* W2 = (const float*)d_in[16];
    const float* b2 = (const float*)d_in[17];

    float* Dsc = (float*)d_out;   // [4, 256, 1024] — doubles as the output

    float *Q, *K, *V, *Xatt, *Msg, *Y1;
    cudaGetSymbolAddress((void**)&Q,    g_Q);
    cudaGetSymbolAddress((void**)&K,    g_K);
    cudaGetSymbolAddress((void**)&V,    g_V);
    cudaGetSymbolAddress((void**)&Xatt, g_Xatt);
    cudaGetSymbolAddress((void**)&Msg,  g_Msg);
    cudaGetSymbolAddress((void**)&Y1,   g_Y1);

    static const int ATTN_SMEM = (64 * 68 + 64 * 72 + 64 * 72 + 64 * 68) * 4; // 71680 B
    cudaFuncSetAttribute(attn_mma, cudaFuncAttributeMaxDynamicSharedMemorySize, ATTN_SMEM);

    size_t descBytes = (size_t)2 * Dd * NN * sizeof(float);
    cudaMemcpyAsync(Dsc,               desc0, descBytes, cudaMemcpyDeviceToDevice, 0);
    cudaMemcpyAsync(Dsc + 2 * Dd * NN, desc1, descBytes, cudaMemcpyDeviceToDevice, 0);

    static const int crossFlag[LL] = {0, 1, 0, 1, 0, 1};

    for (int i = 0; i < LL; i++) {
        int xm = crossFlag[i] ? 2 : 0;
        const float* Wqi = Wq + (size_t)i * Dd * Dd;
        const float* bqi = bq + (size_t)i * Dd;
        const float* Wki = Wk + (size_t)i * Dd * Dd;
        const float* bki = bk + (size_t)i * Dd;
        const float* Wvi = Wv + (size_t)i * Dd * Dd;
        const float* bvi = bv + (size_t)i * Dd;
        const float* Wmi = Wm + (size_t)i * Dd * Dd;
        const float* bmi = bm + (size_t)i * Dd;
        const float* W1i = W1 + (size_t)i * D2 * D2;
        const float* b1i = b1 + (size_t)i * D2;
        const float* g1i = g1 + (size_t)i * D2;
        const float* be1i = be1 + (size_t)i * D2;
        const float* W2i = W2 + (size_t)i * Dd * D2;
        const float* b2i = b2 + (size_t)i * Dd;

        // Fused Q/K/V projections (K/V read swapped halves for cross layers)
        qkv_mma<<<dim3(16, 6, 4), 256>>>(Wqi, bqi, Wki, bki, Wvi, bvi,
                                         Dsc, xm, Q, K, V);

        attn_mma<<<dim3(16, 16), 128, ATTN_SMEM>>>(Q, K, V, M0, M1, Xatt);

        // merge conv
        conv_mma<0, 0><<<dim3(16, 2, 4), 256>>>(Wmi, bmi, Xatt, nullptr, Dd, Msg, Dd, 0);

        // MLP: conv1 (concat [x; msg]), BN stats, conv2 with fused BN+ReLU on load (+residual)
        conv_mma<0, 1><<<dim3(16, 4, 4), 256>>>(W1i, b1i, Dsc, Msg, D2, Y1, D2, 0);
        bn_stats<<<D2, 256>>>(Y1, g1i, be1i);
        conv_mma<1, 0><<<dim3(16, 2, 4), 256>>>(W2i, b2i, Y1, nullptr, D2, Dsc, Dd, 1);
    }
}

// round 6
// speedup vs baseline: 2.3988x; 1.0671x over previous
#include <cuda_runtime.h>
#include <cstdint>

#define B4   4      // 2*BS concatenated batch
#define Dd   256    // feature dim
#define D2   512
#define NN   1024   // keypoints
#define LL   6

// Scratch (device globals; no allocation allowed)
__device__ float g_Q[B4 * Dd * NN];
__device__ float g_K[B4 * Dd * NN];
__device__ float g_V[B4 * Dd * NN];
__device__ float g_Xatt[B4 * Dd * NN];
__device__ float g_Msg[B4 * Dd * NN];
__device__ float g_Y1[B4 * D2 * NN];
__device__ float g_scale[D2];
__device__ float g_shift[D2];

__device__ __forceinline__ uint32_t f2tf(float f) {
    uint32_t u; asm("cvt.rna.tf32.f32 %0, %1;" : "=r"(u) : "f"(f)); return u;
}
__device__ __forceinline__ void mma8(float c[4], const uint32_t a[4], const uint32_t b[2]) {
    asm volatile("mma.sync.aligned.m16n8k8.row.col.f32.tf32.tf32.f32 "
        "{%0,%1,%2,%3}, {%4,%5,%6,%7}, {%8,%9}, {%0,%1,%2,%3};"
        : "+f"(c[0]), "+f"(c[1]), "+f"(c[2]), "+f"(c[3])
        : "r"(a[0]), "r"(a[1]), "r"(a[2]), "r"(a[3]), "r"(b[0]), "r"(b[1]));
}

// ---------------------------------------------------------------------------
// tf32 GEMM core. Block tile BM x 128, BK=16, double-buffered.
// 8 warps (2x4), warp tile (BM/2) x 32. A smem [m][k] stride 20
// (frag LDS bank = (20g+q)%32, conflict-free), B smem [k][n] stride 136
// (bank = (8q+g)%32, conflict-free).
// ---------------------------------------------------------------------------
template<int BM, int BNRELU, int CONCAT>
__device__ __forceinline__ void gemm_core(
    const float* __restrict__ Wp, int I,
    const float* __restrict__ XA, const float* __restrict__ XB,
    int col0, uint32_t (*As)[BM][20], uint32_t (*Bs)[16][136],
    float acc[BM / 32][4][4])
{
    constexpr int MT  = BM / 32;
    constexpr int ANV = (BM == 128) ? 2 : 1;
    int t = threadIdx.x;
    int lane = t & 31, w = t >> 5;
    int g = lane >> 2, q = lane & 3;
    int warp_m = (w >> 2) * (BM / 2), warp_n = (w & 3) * 32;
    int ar = (BM == 128) ? (t >> 1) : (t >> 2);
    int ak = (BM == 128) ? (t & 1) * 8 : (t & 3) * 4;
    int bk = t >> 4, bn = (t & 15) * 8;

    float4 aReg[2];
    float4 bReg[2];
    float bSc = 0.f, bSh = 0.f;

    auto load_tile = [&](int k0) {
        #pragma unroll
        for (int u = 0; u < ANV; u++)
            aReg[u] = *(const float4*)&Wp[(size_t)ar * I + k0 + ak + u * 4];
        int ch = k0 + bk;
        const float* src = XA; int chl = ch;
        if (CONCAT && ch >= 256) { src = XB; chl = ch - 256; }
        const float* gp = &src[(size_t)chl * NN + col0 + bn];
        if (BNRELU) { bSc = g_scale[ch]; bSh = g_shift[ch]; }
        bReg[0] = *(const float4*)gp;
        bReg[1] = *(const float4*)(gp + 4);
    };
    auto store_tile = [&](int buf) {
        #pragma unroll
        for (int u = 0; u < ANV; u++) {
            uint4 s;
            s.x = f2tf(aReg[u].x); s.y = f2tf(aReg[u].y);
            s.z = f2tf(aReg[u].z); s.w = f2tf(aReg[u].w);
            *(uint4*)&As[buf][ar][ak + u * 4] = s;
        }
        #pragma unroll
        for (int u = 0; u < 2; u++) {
            float4 xv = bReg[u];
            if (BNRELU) {
                xv.x = fmaxf(fmaf(xv.x, bSc, bSh), 0.f);
                xv.y = fmaxf(fmaf(xv.y, bSc, bSh), 0.f);
                xv.z = fmaxf(fmaf(xv.z, bSc, bSh), 0.f);
                xv.w = fmaxf(fmaf(xv.w, bSc, bSh), 0.f);
            }
            uint4 s;
            s.x = f2tf(xv.x); s.y = f2tf(xv.y);
            s.z = f2tf(xv.z); s.w = f2tf(xv.w);
            *(uint4*)&Bs[buf][bk][bn + u * 4] = s;
        }
    };

    int nk = I >> 4;
    load_tile(0);
    store_tile(0);
    __syncthreads();

    for (int kt = 0; kt < nk; kt++) {
        int cur = kt & 1;
        if (kt + 1 < nk) load_tile((kt + 1) << 4);

        #pragma unroll
        for (int ks = 0; ks < 16; ks += 8) {
            uint32_t bfr[4][2];
            #pragma unroll
            for (int nt = 0; nt < 4; nt++) {
                int n = warp_n + nt * 8 + g;
                bfr[nt][0] = Bs[cur][ks + q][n];
                bfr[nt][1] = Bs[cur][ks + q + 4][n];
            }
            #pragma unroll
            for (int mt = 0; mt < MT; mt++) {
                int m = warp_m + mt * 16 + g;
                uint32_t a[4];
                a[0] = As[cur][m][ks + q];
                a[1] = As[cur][m + 8][ks + q];
                a[2] = As[cur][m][ks + q + 4];
                a[3] = As[cur][m + 8][ks + q + 4];
                #pragma unroll
                for (int nt = 0; nt < 4; nt++)
                    mma8(acc[mt][nt], a, bfr[nt]);
            }
        }
        if (kt + 1 < nk) store_tile(cur ^ 1);
        __syncthreads();
    }
}

template<int BM>
__device__ __forceinline__ void gemm_epilogue(
    float acc[BM / 32][4][4], const float* __restrict__ bias,
    float* __restrict__ Ob, int row0, int col0, int addOut)
{
    constexpr int MT = BM / 32;
    int t = threadIdx.x; int lane = t & 31; int w = t >> 5;
    int g = lane >> 2, q = lane & 3;
    int warp_m = (w >> 2) * (BM / 2), warp_n = (w & 3) * 32;
    #pragma unroll
    for (int mt = 0; mt < MT; mt++) {
        #pragma unroll
        for (int half = 0; half < 2; half++) {
            int r = row0 + warp_m + mt * 16 + g + half * 8;
            float bb = bias[r];
            #pragma unroll
            for (int nt = 0; nt < 4; nt++) {
                int c = col0 + warp_n + nt * 8 + 2 * q;
                float* p = &Ob[(size_t)r * NN + c];
                float v0 = acc[mt][nt][half * 2 + 0] + bb;
                float v1 = acc[mt][nt][half * 2 + 1] + bb;
                if (addOut) { float2 e = *(const float2*)p; v0 += e.x; v1 += e.y; }
                float2 o; o.x = v0; o.y = v1;
                *(float2*)p = o;
            }
        }
    }
}

// Fused Q/K/V projection: logical rows 0-255 = Q, 256-511 = K, 512-767 = V.
__global__ __launch_bounds__(256, 2) void qkv_mma(
    const float* __restrict__ Wq, const float* __restrict__ bq,
    const float* __restrict__ Wk, const float* __restrict__ bk,
    const float* __restrict__ Wv, const float* __restrict__ bv,
    const float* __restrict__ X, int xorMask,
    float* __restrict__ Qo, float* __restrict__ Ko, float* __restrict__ Vo)
{
    __shared__ uint32_t As[2][128][20];
    __shared__ uint32_t Bs[2][16][136];
    int b    = blockIdx.z;
    int row0 = blockIdx.y * 128;
    int col0 = blockIdx.x * 128;
    int sel  = row0 >> 8;
    int lrow0 = row0 & 255;
    const float* W; const float* bias; float* Out; int xb;
    if (sel == 0)      { W = Wq; bias = bq; Out = Qo; xb = b; }
    else if (sel == 1) { W = Wk; bias = bk; Out = Ko; xb = b ^ xorMask; }
    else               { W = Wv; bias = bv; Out = Vo; xb = b ^ xorMask; }
    const float* XA = X + (size_t)xb * Dd * NN;
    float acc[4][4][4] = {};
    gemm_core<128, 0, 0>(W + (size_t)lrow0 * Dd, Dd, XA, nullptr, col0, As, Bs, acc);
    gemm_epilogue<128>(acc, bias, Out + (size_t)b * Dd * NN, lrow0, col0, 0);
}

template<int BM, int BNRELU, int CONCAT>
__global__ __launch_bounds__(256, 2) void conv_mma(
    const float* __restrict__ W, const float* __restrict__ bias,
    const float* __restrict__ X, const float* __restrict__ X2,
    int I, float* __restrict__ Out, int O, int addOut)
{
    __shared__ uint32_t As[2][BM][20];
    __shared__ uint32_t Bs[2][16][136];
    int b    = blockIdx.z;
    int row0 = blockIdx.y * BM;
    int col0 = blockIdx.x * 128;
    const float* XA = X + (size_t)b * (CONCAT ? 256 : I) * NN;
    const float* XB = CONCAT ? X2 + (size_t)b * 256 * NN : nullptr;
    float acc[BM / 32][4][4] = {};
    gemm_core<BM, BNRELU, CONCAT>(W + (size_t)row0 * I, I, XA, XB, col0, As, Bs, acc);
    gemm_epilogue<BM>(acc, bias, Out + (size_t)b * O * NN, row0, col0, addOut);
}

// ---------------------------------------------------------------------------
// Flash attention with tf32 mma for S = Q^T K and O = P V.
// Block: 64 q-rows x 64 kv-cols, 128 threads (4 warps). Warp w owns rows
// [16w, 16w+16) and ALL 64 cols -> softmax row reductions stay inside a
// lane quad (shfl xor 1,2). Online-softmax state in registers.
// ---------------------------------------------------------------------------
__global__ __launch_bounds__(128) void attn_mma(
    const float* __restrict__ Q, const float* __restrict__ K,
    const float* __restrict__ V,
    const float* __restrict__ M0, const float* __restrict__ M1,
    float* __restrict__ Xatt)
{
    extern __shared__ uint32_t smu[];
    uint32_t (*Qs)[68] = (uint32_t(*)[68])smu;                       // [n][d]
    uint32_t (*Ks)[72] = (uint32_t(*)[72])(smu + 64 * 68);           // [d][m]
    uint32_t (*Vs)[72] = (uint32_t(*)[72])(smu + 64 * 68 + 64 * 72); // [m][d]
    uint32_t (*Ps)[68] = (uint32_t(*)[68])(smu + 64 * 68 + 2 * 64 * 72); // [n][m]
    float    (*Osf)[68] = (float(*)[68])Ps;                          // staging alias

    int bh = blockIdx.y; int b = bh >> 2, h = bh & 3;
    int n0 = blockIdx.x * 64;
    int t = threadIdx.x;
    int lane = t & 31, w = t >> 5;
    int g = lane >> 2, q = lane & 3;
    int rowb = w * 16;

    const float* Qb = Q + (size_t)b * Dd * NN;
    const float* Kb = K + (size_t)b * Dd * NN;
    const float* Vb = V + (size_t)b * Dd * NN;
    const float* Mb = (b < 2) ? M0 + (size_t)b * NN * NN
                              : M1 + (size_t)(b - 2) * NN * NN;

    // Load Q tile -> Qs[n][d], tf32, pre-scaled by 1/8
    {
        int d = t >> 1, nc = (t & 1) * 32;
        const float* gp = &Qb[(size_t)(d * 4 + h) * NN + n0 + nc];
        #pragma unroll
        for (int u = 0; u < 8; u++) {
            float4 v = *(const float4*)(gp + u * 4);
            Qs[nc + u * 4 + 0][d] = f2tf(v.x * 0.125f);
            Qs[nc + u * 4 + 1][d] = f2tf(v.y * 0.125f);
            Qs[nc + u * 4 + 2][d] = f2tf(v.z * 0.125f);
            Qs[nc + u * 4 + 3][d] = f2tf(v.w * 0.125f);
        }
    }

    float oacc[8][4] = {};
    float m0r = -1e30f, m1r = -1e30f, l0 = 0.f, l1 = 0.f;
    int r0g = n0 + rowb + g;
    int r1g = r0g + 8;

    for (int mt = 0; mt < NN; mt += 64) {
        __syncthreads();
        {
            int d = t >> 1, mc = (t & 1) * 32;
            const float* gk = &Kb[(size_t)(d * 4 + h) * NN + mt + mc];
            const float* gv = &Vb[(size_t)(d * 4 + h) * NN + mt + mc];
            #pragma unroll
            for (int u = 0; u < 8; u++) {
                float4 kv = *(const float4*)(gk + u * 4);
                uint4 s;
                s.x = f2tf(kv.x); s.y = f2tf(kv.y); s.z = f2tf(kv.z); s.w = f2tf(kv.w);
                *(uint4*)&Ks[d][mc + u * 4] = s;
            }
            #pragma unroll
            for (int u = 0; u < 8; u++) {
                float4 vv = *(const float4*)(gv + u * 4);
                Vs[mc + u * 4 + 0][d] = f2tf(vv.x);
                Vs[mc + u * 4 + 1][d] = f2tf(vv.y);
                Vs[mc + u * 4 + 2][d] = f2tf(vv.z);
                Vs[mc + u * 4 + 3][d] = f2tf(vv.w);
            }
        }
        __syncthreads();

        // ---- S = Q^T K ----
        float sacc[8][4] = {};
        #pragma unroll
        for (int ks = 0; ks < 8; ks++) {
            int kk = ks * 8;
            uint32_t a[4];
            a[0] = Qs[rowb + g][kk + q];
            a[1] = Qs[rowb + g + 8][kk + q];
            a[2] = Qs[rowb + g][kk + q + 4];
            a[3] = Qs[rowb + g + 8][kk + q + 4];
            #pragma unroll
            for (int nf = 0; nf < 8; nf++) {
                uint32_t bb[2];
                bb[0] = Ks[kk + q][nf * 8 + g];
                bb[1] = Ks[kk + q + 4][nf * 8 + g];
                mma8(sacc[nf], a, bb);
            }
        }

        // ---- mask + online softmax ----
        const float* mr0 = Mb + (size_t)r0g * NN + mt;
        const float* mr1 = Mb + (size_t)r1g * NN + mt;
        float v0[16], v1[16];
        float rm0 = -1e30f, rm1 = -1e30f;
        #pragma unroll
        for (int nf = 0; nf < 8; nf++) {
            int c = nf * 8 + 2 * q;
            float2 k0v = *(const float2*)&mr0[c];
            float2 k1v = *(const float2*)&mr1[c];
            v0[2 * nf]     = sacc[nf][0] * k0v.x;
            v0[2 * nf + 1] = sacc[nf][1] * k0v.y;
            v1[2 * nf]     = sacc[nf][2] * k1v.x;
            v1[2 * nf + 1] = sacc[nf][3] * k1v.y;
            rm0 = fmaxf(rm0, fmaxf(v0[2 * nf], v0[2 * nf + 1]));
            rm1 = fmaxf(rm1, fmaxf(v1[2 * nf], v1[2 * nf + 1]));
        }
        rm0 = fmaxf(rm0, __shfl_xor_sync(0xffffffffu, rm0, 1));
        rm0 = fmaxf(rm0, __shfl_xor_sync(0xffffffffu, rm0, 2));
        rm1 = fmaxf(rm1, __shfl_xor_sync(0xffffffffu, rm1, 1));
        rm1 = fmaxf(rm1, __shfl_xor_sync(0xffffffffu, rm1, 2));
        float nm0 = fmaxf(m0r, rm0), nm1 = fmaxf(m1r, rm1);
        float rs0 = 0.f, rs1 = 0.f;
        #pragma unroll
        for (int i = 0; i < 16; i++) {
            v0[i] = __expf(v0[i] - nm0); rs0 += v0[i];
            v1[i] = __expf(v1[i] - nm1); rs1 += v1[i];
        }
        rs0 += __shfl_xor_sync(0xffffffffu, rs0, 1);
        rs0 += __shfl_xor_sync(0xffffffffu, rs0, 2);
        rs1 += __shfl_xor_sync(0xffffffffu, rs1, 1);
        rs1 += __shfl_xor_sync(0xffffffffu, rs1, 2);
        float f0 = __expf(m0r - nm0), f1 = __expf(m1r - nm1);
        m0r = nm0; m1r = nm1;
        l0 = l0 * f0 + rs0;
        l1 = l1 * f1 + rs1;
        #pragma unroll
        for (int df = 0; df < 8; df++) {
            oacc[df][0] *= f0; oacc[df][1] *= f0;
            oacc[df][2] *= f1; oacc[df][3] *= f1;
        }
        #pragma unroll
        for (int nf = 0; nf < 8; nf++) {
            uint2 p0, p1;
            p0.x = f2tf(v0[2 * nf]); p0.y = f2tf(v0[2 * nf + 1]);
            p1.x = f2tf(v1[2 * nf]); p1.y = f2tf(v1[2 * nf + 1]);
            *(uint2*)&Ps[rowb + g][nf * 8 + 2 * q] = p0;
            *(uint2*)&Ps[rowb + g + 8][nf * 8 + 2 * q] = p1;
        }
        __syncthreads();

        // ---- O += P V ----
        #pragma unroll
        for (int ks = 0; ks < 8; ks++) {
            int kk = ks * 8;
            uint32_t a[4];
            a[0] = Ps[rowb + g][kk + q];
            a[1] = Ps[rowb + g + 8][kk + q];
            a[2] = Ps[rowb + g][kk + q + 4];
            a[3] = Ps[rowb + g + 8][kk + q + 4];
            #pragma unroll
            for (int df = 0; df < 8; df++) {
                uint32_t bb[2];
                bb[0] = Vs[kk + q][df * 8 + g];
                bb[1] = Vs[kk + q + 4][df * 8 + g];
                mma8(oacc[df], a, bb);
            }
        }
    }

    // ---- normalize, stage [d][n], coalesced store ----
    __syncthreads();
    {
        float i0 = 1.0f / l0, i1 = 1.0f / l1;
        #pragma unroll
        for (int df = 0; df < 8; df++) {
            int d0 = df * 8 + 2 * q;
            Osf[d0][rowb + g]         = oacc[df][0] * i0;
            Osf[d0 + 1][rowb + g]     = oacc[df][1] * i0;
            Osf[d0][rowb + g + 8]     = oacc[df][2] * i1;
            Osf[d0 + 1][rowb + g + 8] = oacc[df][3] * i1;
        }
    }
    __syncthreads();
    {
        int d = t >> 1, nc = (t & 1) * 32;
        float* op = &Xatt[(size_t)b * Dd * NN + (size_t)(d * 4 + h) * NN + n0 + nc];
        #pragma unroll
        for (int u = 0; u < 8; u++)
            *(float4*)(op + u * 4) = *(const float4*)&Osf[d][nc + u * 4];
    }
}

// ---------------------------------------------------------------------------
// BatchNorm1d stats (training mode): over (B=4, N=1024) per channel.
// ---------------------------------------------------------------------------
__global__ __launch_bounds__(256) void bn_stats(
    const float* __restrict__ Y, const float* __restrict__ g, const float* __restrict__ beta)
{
    int c = blockIdx.x;
    int t = threadIdx.x;
    float s = 0.f, sq = 0.f;
    for (int b = 0; b < 4; b++) {
        const float* Yp = Y + (size_t)b * D2 * NN + (size_t)c * NN;
        for (int n = t; n < NN; n += 256) {
            float v = Yp[n];
            s += v; sq += v * v;
        }
    }
    __shared__ float rs[256], rq[256];
    rs[t] = s; rq[t] = sq; __syncthreads();
    #pragma unroll
    for (int st = 128; st > 0; st >>= 1) {
        if (t < st) { rs[t] += rs[t + st]; rq[t] += rq[t + st]; }
        __syncthreads();
    }
    if (t == 0) {
        float mean = rs[0] * (1.0f / 4096.0f);
        float var  = rq[0] * (1.0f / 4096.0f) - mean * mean;
        float rstd = rsqrtf(var + 1e-5f);
        float sc = g[c] * rstd;
        g_scale[c] = sc;
        g_shift[c] = beta[c] - mean * sc;
    }
}

// ---------------------------------------------------------------------------
extern "C" void kernel_launch(void* const* d_in, const int* in_sizes, int n_in,
                              void* d_out, int out_size)
{
    const float* desc0 = (const float*)d_in[0];
    const float* desc1 = (const float*)d_in[1];
    const float* M0    = (const float*)d_in[2];
    const float* M1    = (const float*)d_in[3];
    const float* Wq = (const float*)d_in[4];
    const float* bq = (const float*)d_in[5];
    const float* Wk = (const float*)d_in[6];
    const float* bk = (const float*)d_in[7];
    const float* Wv = (const float*)d_in[8];
    const float* bv = (const float*)d_in[9];
    const float* Wm = (const float*)d_in[10];
    const float* bm = (const float*)d_in[11];
    const float* W1 = (const float*)d_in[12];
    const float* b1 = (const float*)d_in[13];
    const float* g1 = (const float*)d_in[14];
    const float* be1 = (const float*)d_in[15];
    const float* W2 = (const float*)d_in[16];
    const float* b2 = (const float*)d_in[17];

    float* Dsc = (float*)d_out;   // [4, 256, 1024] — doubles as the output

    float *Q, *K, *V, *Xatt, *Msg, *Y1;
    cudaGetSymbolAddress((void**)&Q,    g_Q);
    cudaGetSymbolAddress((void**)&K,    g_K);
    cudaGetSymbolAddress((void**)&V,    g_V);
    cudaGetSymbolAddress((void**)&Xatt, g_Xatt);
    cudaGetSymbolAddress((void**)&Msg,  g_Msg);
    cudaGetSymbolAddress((void**)&Y1,   g_Y1);

    static const int ATTN_SMEM = (64 * 68 + 64 * 72 + 64 * 72 + 64 * 68) * 4; // 71680 B
    cudaFuncSetAttribute(attn_mma, cudaFuncAttributeMaxDynamicSharedMemorySize, ATTN_SMEM);

    size_t descBytes = (size_t)2 * Dd * NN * sizeof(float);
    cudaMemcpyAsync(Dsc,               desc0, descBytes, cudaMemcpyDeviceToDevice, 0);
    cudaMemcpyAsync(Dsc + 2 * Dd * NN, desc1, descBytes, cudaMemcpyDeviceToDevice, 0);

    static const int crossFlag[LL] = {0, 1, 0, 1, 0, 1};

    for (int i = 0; i < LL; i++) {
        int xm = crossFlag[i] ? 2 : 0;
        const float* Wqi = Wq + (size_t)i * Dd * Dd;
        const float* bqi = bq + (size_t)i * Dd;
        const float* Wki = Wk + (size_t)i * Dd * Dd;
        const float* bki = bk + (size_t)i * Dd;
        const float* Wvi = Wv + (size_t)i * Dd * Dd;
        const float* bvi = bv + (size_t)i * Dd;
        const float* Wmi = Wm + (size_t)i * Dd * Dd;
        const float* bmi = bm + (size_t)i * Dd;
        const float* W1i = W1 + (size_t)i * D2 * D2;
        const float* b1i = b1 + (size_t)i * D2;
        const float* g1i = g1 + (size_t)i * D2;
        const float* be1i = be1 + (size_t)i * D2;
        const float* W2i = W2 + (size_t)i * Dd * D2;
        const float* b2i = b2 + (size_t)i * Dd;

        // Fused Q/K/V projections (K/V read swapped halves for cross layers)
        qkv_mma<<<dim3(8, 6, 4), 256>>>(Wqi, bqi, Wki, bki, Wvi, bvi,
                                        Dsc, xm, Q, K, V);

        attn_mma<<<dim3(16, 16), 128, ATTN_SMEM>>>(Q, K, V, M0, M1, Xatt);

        // merge conv (O=256 -> BM=64 grid keeps 128 blocks)
        conv_mma<64, 0, 0><<<dim3(8, 4, 4), 256>>>(Wmi, bmi, Xatt, nullptr, Dd, Msg, Dd, 0);

        // MLP: conv1 (concat [x; msg]), BN stats, conv2 with fused BN+ReLU (+residual)
        conv_mma<128, 0, 1><<<dim3(8, 4, 4), 256>>>(W1i, b1i, Dsc, Msg, D2, Y1, D2, 0);
        bn_stats<<<D2, 256>>>(Y1, g1i, be1i);
        conv_mma<64, 1, 0><<<dim3(8, 4, 4), 256>>>(W2i, b2i, Y1, nullptr, D2, Dsc, Dd, 1);
    }
}